// round 1
// baseline (speedup 1.0000x reference)
#include <cuda_runtime.h>
#include <math.h>

// Problem constants
#define Bsz   4
#define Ssz   2048
#define Dsz   1024
#define Hsz   16
#define DKsz  64
#define DFFsz 4096
#define Msz   (Bsz*Ssz)   // 8192 rows

// ---------------- scratch (static device globals; no allocation) ----------------
__device__ float g_q  [(size_t)Msz*Dsz];
__device__ float g_k  [(size_t)Msz*Dsz];
__device__ float g_v  [(size_t)Msz*Dsz];
__device__ float g_ctx[(size_t)Msz*Dsz];
__device__ float g_tmp[(size_t)Msz*Dsz];   // attn_out, later ff2 out
__device__ float g_x1 [(size_t)Msz*Dsz];
__device__ float g_ff [(size_t)Msz*DFFsz];
__device__ float g_gate[(size_t)Msz*Hsz];

// ---------------- generic tiled SGEMM: C = A[MxK] @ W[KxN] + bias, act ----------
// BM=BN=128, BK=16, 256 threads, 8x8 microtile per thread.
__global__ __launch_bounds__(256, 2)
void gemm_kernel(const float* __restrict__ A, const float* __restrict__ W,
                 const float* __restrict__ bias, float* __restrict__ C,
                 int M, int N, int K, int act)
{
    __shared__ __align__(16) float As[16][132];   // [k][m], padded
    __shared__ __align__(16) float Bs[16][128];   // [k][n]

    int tid = threadIdx.x;
    int tx = tid & 15, ty = tid >> 4;
    int row0 = blockIdx.y * 128, col0 = blockIdx.x * 128;

    float acc[8][8];
    #pragma unroll
    for (int i = 0; i < 8; i++)
        #pragma unroll
        for (int j = 0; j < 8; j++) acc[i][j] = 0.0f;

    int aK  = tid & 15;    // k within tile
    int aM0 = tid >> 4;    // row base, +16 per pass
    int bN  = tid & 127;
    int bK0 = tid >> 7;    // 0..1, +2 per pass

    const float* Ap = A + (size_t)row0 * K;
    const float* Wp = W + col0;

    for (int k0 = 0; k0 < K; k0 += 16) {
        #pragma unroll
        for (int i = 0; i < 8; i++)
            As[aK][aM0 + i*16] = Ap[(size_t)(aM0 + i*16) * K + (k0 + aK)];
        #pragma unroll
        for (int i = 0; i < 8; i++)
            Bs[bK0 + i*2][bN] = Wp[(size_t)(k0 + bK0 + i*2) * N + bN];
        __syncthreads();

        #pragma unroll
        for (int kk = 0; kk < 16; kk++) {
            float4 a0 = *(const float4*)&As[kk][ty*8];
            float4 a1 = *(const float4*)&As[kk][ty*8 + 4];
            float4 b0 = *(const float4*)&Bs[kk][tx*8];
            float4 b1 = *(const float4*)&Bs[kk][tx*8 + 4];
            float ar[8] = {a0.x,a0.y,a0.z,a0.w,a1.x,a1.y,a1.z,a1.w};
            float br[8] = {b0.x,b0.y,b0.z,b0.w,b1.x,b1.y,b1.z,b1.w};
            #pragma unroll
            for (int i = 0; i < 8; i++)
                #pragma unroll
                for (int j = 0; j < 8; j++)
                    acc[i][j] = fmaf(ar[i], br[j], acc[i][j]);
        }
        __syncthreads();
    }

    #pragma unroll
    for (int i = 0; i < 8; i++) {
        size_t r = (size_t)(row0 + ty*8 + i);
        #pragma unroll
        for (int j = 0; j < 8; j++) {
            int c = col0 + tx*8 + j;
            float vv = acc[i][j] + bias[c];
            if (act) vv = 0.5f * vv * (1.0f + erff(vv * 0.70710678118654752f));
            C[r * (size_t)N + c] = vv;
        }
    }
}

// ---------------- sigmoid gate: gate[m,h] = sigmoid(x[m,:] @ w_g[:,h] + b_g[h]) --
__global__ void gate_kernel(const float* __restrict__ x, const float* __restrict__ wg,
                            const float* __restrict__ bg, float* __restrict__ gate)
{
    int m = blockIdx.x;
    int tid = threadIdx.x;  // 128
    float s[16];
    #pragma unroll
    for (int h = 0; h < 16; h++) s[h] = 0.0f;

    for (int d = tid; d < Dsz; d += 128) {
        float xv = x[(size_t)m * Dsz + d];
        const float* wr = wg + (size_t)d * Hsz;
        #pragma unroll
        for (int h = 0; h < 16; h++) s[h] = fmaf(xv, wr[h], s[h]);
    }

    __shared__ float red[4][16];
    int warp = tid >> 5, lane = tid & 31;
    #pragma unroll
    for (int h = 0; h < 16; h++) {
        float v = s[h];
        for (int off = 16; off; off >>= 1) v += __shfl_xor_sync(0xffffffffu, v, off);
        if (lane == 0) red[warp][h] = v;
    }
    __syncthreads();
    if (tid < 16) {
        float tot = red[0][tid] + red[1][tid] + red[2][tid] + red[3][tid] + bg[tid];
        gate[(size_t)m * Hsz + tid] = 1.0f / (1.0f + __expf(-tot));
    }
}

// ---------------- flash attention: per (b,h,qtile) 64q x 32k tiles --------------
__global__ __launch_bounds__(256)
void flash_kernel(const float* __restrict__ Q, const float* __restrict__ Kg,
                  const float* __restrict__ Vg, const float* __restrict__ gate,
                  const int* __restrict__ mask, float* __restrict__ ctx)
{
    __shared__ __align__(16) float Qs[64][65];  // [d][q]
    __shared__ __align__(16) float KP[64][33];  // Ks[d][kk] -> Ps[q][kk]
    __shared__ __align__(16) float Vs[32][64];  // [kk][d]

    int qt = blockIdx.x, h = blockIdx.y, b = blockIdx.z;
    int tid = threadIdx.x;
    int tx = tid & 15, ty = tid >> 4;
    int dcol = tid & 63;
    size_t hoff = (size_t)h * DKsz;
    size_t rowbase = (size_t)b * Ssz;

    // Load Q tile (64 q x 64 d) transposed
    #pragma unroll
    for (int p = 0; p < 16; p++) {
        int qq = (tid >> 6) + p * 4;
        Qs[dcol][qq] = Q[(rowbase + qt*64 + qq) * Dsz + hoff + dcol];
    }

    float Oa[4][4];
    float mrow[4], lrow[4];
    #pragma unroll
    for (int i = 0; i < 4; i++) {
        mrow[i] = -1e30f; lrow[i] = 0.0f;
        #pragma unroll
        for (int j = 0; j < 4; j++) Oa[i][j] = 0.0f;
    }
    __syncthreads();

    for (int kt = 0; kt < Ssz/32; kt++) {
        // Load K (transposed) and V tiles
        #pragma unroll
        for (int p = 0; p < 8; p++) {
            int kk = (tid >> 6) + p * 4;
            size_t ga = (rowbase + kt*32 + kk) * Dsz + hoff + dcol;
            KP[dcol][kk] = Kg[ga];
            Vs[kk][dcol] = Vg[ga];
        }
        __syncthreads();

        // S = Q K^T for this tile: each thread 4(q) x 2(kk)
        float s0[4], s1[4];
        #pragma unroll
        for (int i = 0; i < 4; i++) { s0[i] = 0.0f; s1[i] = 0.0f; }
        #pragma unroll 16
        for (int d = 0; d < 64; d++) {
            float kv0 = KP[d][2*tx];
            float kv1 = KP[d][2*tx + 1];
            #pragma unroll
            for (int i = 0; i < 4; i++) {
                float qv = Qs[d][4*ty + i];
                s0[i] = fmaf(qv, kv0, s0[i]);
                s1[i] = fmaf(qv, kv1, s1[i]);
            }
        }
        __syncthreads();  // all Ks reads done before Ps overwrites KP

        // scale + mask
        int kb = kt*32 + 2*tx;
        bool mz0 = (mask[rowbase + kb] == 0);
        bool mz1 = (mask[rowbase + kb + 1] == 0);

        float p0[4], p1[4];
        #pragma unroll
        for (int i = 0; i < 4; i++) {
            float a = s0[i] * 0.125f;
            float c = s1[i] * 0.125f;
            if (mz0) a = -1e9f;
            if (mz1) c = -1e9f;
            float mx = fmaxf(a, c);
            #pragma unroll
            for (int off = 1; off < 16; off <<= 1)
                mx = fmaxf(mx, __shfl_xor_sync(0xffffffffu, mx, off));
            float mnew = fmaxf(mrow[i], mx);
            float al = __expf(mrow[i] - mnew);
            p0[i] = __expf(a - mnew);
            p1[i] = __expf(c - mnew);
            float rs = p0[i] + p1[i];
            #pragma unroll
            for (int off = 1; off < 16; off <<= 1)
                rs += __shfl_xor_sync(0xffffffffu, rs, off);
            lrow[i] = lrow[i] * al + rs;
            mrow[i] = mnew;
            #pragma unroll
            for (int j = 0; j < 4; j++) Oa[i][j] *= al;
        }
        // write P into KP as Ps[q][kk]
        #pragma unroll
        for (int i = 0; i < 4; i++) {
            KP[4*ty + i][2*tx]     = p0[i];
            KP[4*ty + i][2*tx + 1] = p1[i];
        }
        __syncthreads();

        // O += P @ V : thread owns rows 4*ty..+3, cols 4*tx..+3
        #pragma unroll 8
        for (int kk = 0; kk < 32; kk++) {
            float4 vv = *(const float4*)&Vs[kk][4*tx];
            #pragma unroll
            for (int i = 0; i < 4; i++) {
                float pv = KP[4*ty + i][kk];
                Oa[i][0] = fmaf(pv, vv.x, Oa[i][0]);
                Oa[i][1] = fmaf(pv, vv.y, Oa[i][1]);
                Oa[i][2] = fmaf(pv, vv.z, Oa[i][2]);
                Oa[i][3] = fmaf(pv, vv.w, Oa[i][3]);
            }
        }
        __syncthreads();  // PV reads done before next tile loads
    }

    // finalize: O /= l, * gate, write ctx[b,s,h*64+d]
    #pragma unroll
    for (int i = 0; i < 4; i++) {
        int q = qt*64 + 4*ty + i;
        float gv = gate[(rowbase + q) * Hsz + h];
        float f = gv / lrow[i];
        size_t obase = (rowbase + q) * Dsz + hoff + 4*tx;
        #pragma unroll
        for (int j = 0; j < 4; j++)
            ctx[obase + j] = Oa[i][j] * f;
    }
}

// ---------------- fused residual add + LayerNorm (one row per block) -----------
__global__ __launch_bounds__(256)
void add_ln_kernel(const float* __restrict__ a, const float* __restrict__ bsrc,
                   const float* __restrict__ g, const float* __restrict__ beta,
                   float* __restrict__ out)
{
    int row = blockIdx.x;
    int tid = threadIdx.x;
    __shared__ float buf[Dsz];
    __shared__ float rsum[8], rsq[8];

    size_t base = (size_t)row * Dsz;
    float ls = 0.0f, lq = 0.0f;
    for (int d = tid; d < Dsz; d += 256) {
        float v = a[base + d] + bsrc[base + d];
        buf[d] = v;
        ls += v; lq += v * v;
    }
    int warp = tid >> 5, lane = tid & 31;
    for (int off = 16; off; off >>= 1) {
        ls += __shfl_xor_sync(0xffffffffu, ls, off);
        lq += __shfl_xor_sync(0xffffffffu, lq, off);
    }
    if (lane == 0) { rsum[warp] = ls; rsq[warp] = lq; }
    __syncthreads();
    float ts = 0.0f, tq = 0.0f;
    #pragma unroll
    for (int w = 0; w < 8; w++) { ts += rsum[w]; tq += rsq[w]; }
    float mean = ts * (1.0f / Dsz);
    float var  = tq * (1.0f / Dsz) - mean * mean;
    float rstd = rsqrtf(var + 1e-5f);
    for (int d = tid; d < Dsz; d += 256)
        out[base + d] = (buf[d] - mean) * rstd * g[d] + beta[d];
}

// ---------------- launch ----------------
extern "C" void kernel_launch(void* const* d_in, const int* in_sizes, int n_in,
                              void* d_out, int out_size)
{
    const float* x     = (const float*)d_in[0];
    const float* w_q   = (const float*)d_in[1];
    const float* b_q   = (const float*)d_in[2];
    const float* w_k   = (const float*)d_in[3];
    const float* b_k   = (const float*)d_in[4];
    const float* w_v   = (const float*)d_in[5];
    const float* b_v   = (const float*)d_in[6];
    const float* w_o   = (const float*)d_in[7];
    const float* b_o   = (const float*)d_in[8];
    const float* w_g   = (const float*)d_in[9];
    const float* b_g   = (const float*)d_in[10];
    const float* w1    = (const float*)d_in[11];
    const float* b1    = (const float*)d_in[12];
    const float* w2    = (const float*)d_in[13];
    const float* b2    = (const float*)d_in[14];
    const float* g1    = (const float*)d_in[15];
    const float* beta1 = (const float*)d_in[16];
    const float* g2    = (const float*)d_in[17];
    const float* beta2 = (const float*)d_in[18];
    const int*   mask  = (const int*)  d_in[19];
    float* out = (float*)d_out;

    float *q, *k, *v, *ctx, *tmp, *x1, *ff, *gate;
    cudaGetSymbolAddress((void**)&q,    g_q);
    cudaGetSymbolAddress((void**)&k,    g_k);
    cudaGetSymbolAddress((void**)&v,    g_v);
    cudaGetSymbolAddress((void**)&ctx,  g_ctx);
    cudaGetSymbolAddress((void**)&tmp,  g_tmp);
    cudaGetSymbolAddress((void**)&x1,   g_x1);
    cudaGetSymbolAddress((void**)&ff,   g_ff);
    cudaGetSymbolAddress((void**)&gate, g_gate);

    dim3 gSq(Dsz/128, Msz/128);      // (8, 64)
    dim3 gF1(DFFsz/128, Msz/128);    // (32, 64)

    gemm_kernel<<<gSq, 256>>>(x, w_q, b_q, q, Msz, Dsz, Dsz, 0);
    gemm_kernel<<<gSq, 256>>>(x, w_k, b_k, k, Msz, Dsz, Dsz, 0);
    gemm_kernel<<<gSq, 256>>>(x, w_v, b_v, v, Msz, Dsz, Dsz, 0);
    gate_kernel<<<Msz, 128>>>(x, w_g, b_g, gate);
    flash_kernel<<<dim3(Ssz/64, Hsz, Bsz), 256>>>(q, k, v, gate, mask, ctx);
    gemm_kernel<<<gSq, 256>>>(ctx, w_o, b_o, tmp, Msz, Dsz, Dsz, 0);
    add_ln_kernel<<<Msz, 256>>>(x, tmp, g1, beta1, x1);
    gemm_kernel<<<gF1, 256>>>(x1, w1, b1, ff, Msz, DFFsz, Dsz, 1);
    gemm_kernel<<<gSq, 256>>>(ff, w2, b2, tmp, Msz, Dsz, DFFsz, 0);
    add_ln_kernel<<<Msz, 256>>>(x1, tmp, g2, beta2, out);
}

// round 3
// speedup vs baseline: 1.7983x; 1.7983x over previous
#include <cuda_runtime.h>
#include <cuda_bf16.h>
#include <math.h>
#include <cstdint>

// Problem constants
#define Bsz   4
#define Ssz   2048
#define Dsz   1024
#define Hsz   16
#define DKsz  64
#define DFFsz 4096
#define Msz   (Bsz*Ssz)   // 8192 rows

typedef __nv_bfloat16 bf16;

// ---------------- scratch (static device globals; no allocation) ----------------
__device__ float g_q  [(size_t)Msz*Dsz];
__device__ float g_k  [(size_t)Msz*Dsz];
__device__ float g_v  [(size_t)Msz*Dsz];
__device__ float g_ctx[(size_t)Msz*Dsz];
__device__ float g_tmp[(size_t)Msz*Dsz];   // attn_out, later ff2 out
__device__ float g_x1 [(size_t)Msz*Dsz];
__device__ float g_ff [(size_t)Msz*DFFsz];
__device__ float g_gate[(size_t)Msz*Hsz];

// bf16 hi/lo split buffers
__device__ bf16 g_xh [(size_t)Msz*Dsz];
__device__ bf16 g_xl [(size_t)Msz*Dsz];
__device__ bf16 g_ctxh[(size_t)Msz*Dsz];
__device__ bf16 g_ctxl[(size_t)Msz*Dsz];
__device__ bf16 g_x1h[(size_t)Msz*Dsz];
__device__ bf16 g_x1l[(size_t)Msz*Dsz];
__device__ bf16 g_ffh[(size_t)Msz*DFFsz];
__device__ bf16 g_ffl[(size_t)Msz*DFFsz];
__device__ bf16 g_wqh[(size_t)Dsz*Dsz],  g_wql[(size_t)Dsz*Dsz];
__device__ bf16 g_wkh[(size_t)Dsz*Dsz],  g_wkl[(size_t)Dsz*Dsz];
__device__ bf16 g_wvh[(size_t)Dsz*Dsz],  g_wvl[(size_t)Dsz*Dsz];
__device__ bf16 g_woh[(size_t)Dsz*Dsz],  g_wol[(size_t)Dsz*Dsz];
__device__ bf16 g_w1h[(size_t)Dsz*DFFsz], g_w1l[(size_t)Dsz*DFFsz];
__device__ bf16 g_w2h[(size_t)DFFsz*Dsz], g_w2l[(size_t)DFFsz*Dsz];

// ---------------- fp32 -> bf16 hi/lo split ----------------
__global__ __launch_bounds__(256)
void split_kernel(const float* __restrict__ in, bf16* __restrict__ hi,
                  bf16* __restrict__ lo, int n4)
{
    int i = blockIdx.x * 256 + threadIdx.x;
    if (i >= n4) return;
    float4 v = ((const float4*)in)[i];
    bf16 h0 = __float2bfloat16(v.x);
    bf16 h1 = __float2bfloat16(v.y);
    bf16 h2 = __float2bfloat16(v.z);
    bf16 h3 = __float2bfloat16(v.w);
    bf16 l0 = __float2bfloat16(v.x - __bfloat162float(h0));
    bf16 l1 = __float2bfloat16(v.y - __bfloat162float(h1));
    bf16 l2 = __float2bfloat16(v.z - __bfloat162float(h2));
    bf16 l3 = __float2bfloat16(v.w - __bfloat162float(h3));
    __nv_bfloat162* hp = (__nv_bfloat162*)hi;
    __nv_bfloat162* lp = (__nv_bfloat162*)lo;
    hp[2*i]   = __halves2bfloat162(h0, h1);
    hp[2*i+1] = __halves2bfloat162(h2, h3);
    lp[2*i]   = __halves2bfloat162(l0, l1);
    lp[2*i+1] = __halves2bfloat162(l2, l3);
}

// ---------------- bf16x3 tensor-core GEMM: C = A @ W + bias (+GELU) ----------
// A = Ah + Al (row-major M x K), W = Wh + Wl (row-major K x N)
// acc = Ah*Wh + Al*Wh + Ah*Wl    (lo*lo dropped; rel err ~2^-16)
// BM=BN=128, BK=16, 256 threads = 8 warps (2 M x 4 N), warp tile 64x32.

__device__ __forceinline__ void cp16(uint32_t dst, const void* src) {
    asm volatile("cp.async.ca.shared.global [%0], [%1], 16;\n" :: "r"(dst), "l"(src));
}
__device__ __forceinline__ void cp_commit() {
    asm volatile("cp.async.commit_group;\n");
}
__device__ __forceinline__ void cp_wait0() {
    asm volatile("cp.async.wait_group 0;\n");
}
__device__ __forceinline__ void ldsm4(uint32_t* r, uint32_t addr) {
    asm volatile("ldmatrix.sync.aligned.m8n8.x4.shared.b16 {%0,%1,%2,%3}, [%4];"
                 : "=r"(r[0]), "=r"(r[1]), "=r"(r[2]), "=r"(r[3]) : "r"(addr));
}
__device__ __forceinline__ void ldsm4t(uint32_t& r0, uint32_t& r1,
                                       uint32_t& r2, uint32_t& r3, uint32_t addr) {
    asm volatile("ldmatrix.sync.aligned.m8n8.x4.trans.shared.b16 {%0,%1,%2,%3}, [%4];"
                 : "=r"(r0), "=r"(r1), "=r"(r2), "=r"(r3) : "r"(addr));
}
__device__ __forceinline__ void mma16816(float* ac, const uint32_t* a,
                                         uint32_t b0, uint32_t b1) {
    asm volatile(
        "mma.sync.aligned.m16n8k16.row.col.f32.bf16.bf16.f32 "
        "{%0,%1,%2,%3},{%4,%5,%6,%7},{%8,%9},{%0,%1,%2,%3};"
        : "+f"(ac[0]), "+f"(ac[1]), "+f"(ac[2]), "+f"(ac[3])
        : "r"(a[0]), "r"(a[1]), "r"(a[2]), "r"(a[3]), "r"(b0), "r"(b1));
}

#define APAD 24   // 16 + 8 bf16 pad (48B row stride -> conflict-free ldmatrix)
#define WPAD 136  // 128 + 8 pad (272B stride -> conflict-free ldmatrix.trans)

__global__ __launch_bounds__(256)
void gemm_bf16x3_kernel(const bf16* __restrict__ Ah, const bf16* __restrict__ Al,
                        const bf16* __restrict__ Wh, const bf16* __restrict__ Wl,
                        const float* __restrict__ bias, float* __restrict__ C,
                        int M, int N, int K, int act)
{
    __shared__ __align__(16) bf16 sAh[2][128][APAD];
    __shared__ __align__(16) bf16 sAl[2][128][APAD];
    __shared__ __align__(16) bf16 sWh[2][16][WPAD];
    __shared__ __align__(16) bf16 sWl[2][16][WPAD];

    const int tid = threadIdx.x;
    const int row0 = blockIdx.y * 128, col0 = blockIdx.x * 128;

    // global src pointers for this thread's cp.async slots
    const char* pAh = (const char*)(Ah + (size_t)(row0 + (tid>>1)) * K + (tid&1)*8);
    const char* pAl = (const char*)(Al + (size_t)(row0 + (tid>>1)) * K + (tid&1)*8);
    const char* pWh = (const char*)(Wh + (size_t)(tid>>4) * N + col0 + (tid&15)*8);
    const char* pWl = (const char*)(Wl + (size_t)(tid>>4) * N + col0 + (tid&15)*8);

    const uint32_t aAh = (uint32_t)__cvta_generic_to_shared(&sAh[0][0][0]);
    const uint32_t aAl = (uint32_t)__cvta_generic_to_shared(&sAl[0][0][0]);
    const uint32_t aWh = (uint32_t)__cvta_generic_to_shared(&sWh[0][0][0]);
    const uint32_t aWl = (uint32_t)__cvta_generic_to_shared(&sWl[0][0][0]);
    const uint32_t SA = 128*APAD*2, SW = 16*WPAD*2;
    const uint32_t dA = ((tid>>1)*APAD + (tid&1)*8) * 2;
    const uint32_t dW = ((tid>>4)*WPAD + (tid&15)*8) * 2;

    float acc[4][4][4];
    #pragma unroll
    for (int i = 0; i < 4; i++)
        #pragma unroll
        for (int j = 0; j < 4; j++)
            #pragma unroll
            for (int t = 0; t < 4; t++) acc[i][j][t] = 0.0f;

    const int wid = tid >> 5, lane = tid & 31;
    const int wm = wid & 1;       // M offset wm*64
    const int wn = wid >> 1;      // N offset wn*32
    const int lrow = lane & 15, lk = (lane >> 4) * 8;
    const uint32_t offA0 = (uint32_t)(((wm*64 + lrow) * APAD + lk) * 2);
    const uint32_t offB0 = (uint32_t)(((lane & 15) * WPAD + wn*32 + (lane>>4)*8) * 2);

    const int nit = K / 16;

    // prologue: stage 0
    cp16(aAh + dA, pAh);
    cp16(aAl + dA, pAl);
    cp16(aWh + dW, pWh);
    cp16(aWl + dW, pWl);
    cp_commit();

    for (int it = 0; it < nit; ++it) {
        cp_wait0();
        __syncthreads();
        if (it + 1 < nit) {
            uint32_t st = (uint32_t)((it + 1) & 1);
            size_t ka = (size_t)(it + 1) * 16 * 2;             // A byte advance
            size_t kw = (size_t)(it + 1) * 16 * (size_t)N * 2; // W byte advance
            cp16(aAh + st*SA + dA, pAh + ka);
            cp16(aAl + st*SA + dA, pAl + ka);
            cp16(aWh + st*SW + dW, pWh + kw);
            cp16(aWl + st*SW + dW, pWl + kw);
            cp_commit();
        }
        const uint32_t s = (uint32_t)(it & 1);

        // A fragments (hi and lo), 4 m-subtiles of 16
        uint32_t afh[4][4], afl[4][4];
        #pragma unroll
        for (int mi = 0; mi < 4; mi++)
            ldsm4(afh[mi], aAh + s*SA + offA0 + mi*16*APAD*2);
        #pragma unroll
        for (int mi = 0; mi < 4; mi++)
            ldsm4(afl[mi], aAl + s*SA + offA0 + mi*16*APAD*2);

        // B hi fragments: 4 n-subtiles of 8 (two ldmatrix.x4.trans)
        uint32_t bf[4][2];
        #pragma unroll
        for (int ng = 0; ng < 2; ng++)
            ldsm4t(bf[2*ng][0], bf[2*ng][1], bf[2*ng+1][0], bf[2*ng+1][1],
                   aWh + s*SW + offB0 + (uint32_t)(ng*16*2));
        // hi*hi + lo*hi
        #pragma unroll
        for (int mi = 0; mi < 4; mi++)
            #pragma unroll
            for (int ni = 0; ni < 4; ni++) {
                mma16816(acc[mi][ni], afh[mi], bf[ni][0], bf[ni][1]);
                mma16816(acc[mi][ni], afl[mi], bf[ni][0], bf[ni][1]);
            }
        // B lo fragments (reuse regs)
        #pragma unroll
        for (int ng = 0; ng < 2; ng++)
            ldsm4t(bf[2*ng][0], bf[2*ng][1], bf[2*ng+1][0], bf[2*ng+1][1],
                   aWl + s*SW + offB0 + (uint32_t)(ng*16*2));
        // hi*lo
        #pragma unroll
        for (int mi = 0; mi < 4; mi++)
            #pragma unroll
            for (int ni = 0; ni < 4; ni++)
                mma16816(acc[mi][ni], afh[mi], bf[ni][0], bf[ni][1]);
    }

    // epilogue
    #pragma unroll
    for (int mi = 0; mi < 4; mi++) {
        #pragma unroll
        for (int ni = 0; ni < 4; ni++) {
            int c = col0 + wn*32 + ni*8 + (lane & 3)*2;
            float bx = bias[c], by = bias[c + 1];
            #pragma unroll
            for (int rh = 0; rh < 2; rh++) {
                int r = row0 + wm*64 + mi*16 + (lane >> 2) + rh*8;
                float v0 = acc[mi][ni][2*rh]     + bx;
                float v1 = acc[mi][ni][2*rh + 1] + by;
                if (act) {
                    v0 = 0.5f * v0 * (1.0f + erff(v0 * 0.70710678118654752f));
                    v1 = 0.5f * v1 * (1.0f + erff(v1 * 0.70710678118654752f));
                }
                float2 o; o.x = v0; o.y = v1;
                *(float2*)&C[(size_t)r * N + c] = o;
            }
        }
    }
}

// ---------------- sigmoid gate (w_g half staged in smem) ----------------------
// grid (Msz/32, 2), block 256. blockIdx.y selects 8-head group.
__global__ __launch_bounds__(256)
void gate_kernel(const float* __restrict__ x, const float* __restrict__ wg,
                 const float* __restrict__ bg, float* __restrict__ gate)
{
    __shared__ float wgs[Dsz][8];
    int hg = blockIdx.y;
    int tid = threadIdx.x;
    for (int idx = tid; idx < Dsz*8; idx += 256)
        wgs[idx >> 3][idx & 7] = wg[(idx >> 3) * Hsz + hg*8 + (idx & 7)];
    __syncthreads();

    int h = tid & 7, r = tid >> 3;  // 32 rows per block
    int m = blockIdx.x * 32 + r;
    const float4* xr = (const float4*)(x + (size_t)m * Dsz);
    float s = 0.0f;
    #pragma unroll 4
    for (int d4 = 0; d4 < Dsz/4; d4++) {
        float4 xv = xr[d4];
        s = fmaf(xv.x, wgs[d4*4 + 0][h], s);
        s = fmaf(xv.y, wgs[d4*4 + 1][h], s);
        s = fmaf(xv.z, wgs[d4*4 + 2][h], s);
        s = fmaf(xv.w, wgs[d4*4 + 3][h], s);
    }
    s += bg[hg*8 + h];
    gate[(size_t)m * Hsz + hg*8 + h] = 1.0f / (1.0f + __expf(-s));
}

// ---------------- flash attention: per (b,h,qtile) 64q x 32k tiles --------------
__global__ __launch_bounds__(256)
void flash_kernel(const float* __restrict__ Q, const float* __restrict__ Kg,
                  const float* __restrict__ Vg, const float* __restrict__ gate,
                  const int* __restrict__ mask, float* __restrict__ ctx)
{
    __shared__ __align__(16) float Qs[64][65];  // [d][q]
    __shared__ __align__(16) float KP[64][33];  // Ks[d][kk] -> Ps[q][kk]
    __shared__ __align__(16) float Vs[32][64];  // [kk][d]

    int qt = blockIdx.x, h = blockIdx.y, b = blockIdx.z;
    int tid = threadIdx.x;
    int tx = tid & 15, ty = tid >> 4;
    int dcol = tid & 63;
    size_t hoff = (size_t)h * DKsz;
    size_t rowbase = (size_t)b * Ssz;

    #pragma unroll
    for (int p = 0; p < 16; p++) {
        int qq = (tid >> 6) + p * 4;
        Qs[dcol][qq] = Q[(rowbase + qt*64 + qq) * Dsz + hoff + dcol];
    }

    float Oa[4][4];
    float mrow[4], lrow[4];
    #pragma unroll
    for (int i = 0; i < 4; i++) {
        mrow[i] = -1e30f; lrow[i] = 0.0f;
        #pragma unroll
        for (int j = 0; j < 4; j++) Oa[i][j] = 0.0f;
    }
    __syncthreads();

    for (int kt = 0; kt < Ssz/32; kt++) {
        #pragma unroll
        for (int p = 0; p < 8; p++) {
            int kk = (tid >> 6) + p * 4;
            size_t ga = (rowbase + kt*32 + kk) * Dsz + hoff + dcol;
            KP[dcol][kk] = Kg[ga];
            Vs[kk][dcol] = Vg[ga];
        }
        __syncthreads();

        float s0[4], s1[4];
        #pragma unroll
        for (int i = 0; i < 4; i++) { s0[i] = 0.0f; s1[i] = 0.0f; }
        #pragma unroll 16
        for (int d = 0; d < 64; d++) {
            float kv0 = KP[d][2*tx];
            float kv1 = KP[d][2*tx + 1];
            #pragma unroll
            for (int i = 0; i < 4; i++) {
                float qv = Qs[d][4*ty + i];
                s0[i] = fmaf(qv, kv0, s0[i]);
                s1[i] = fmaf(qv, kv1, s1[i]);
            }
        }
        __syncthreads();

        int kb = kt*32 + 2*tx;
        bool mz0 = (mask[rowbase + kb] == 0);
        bool mz1 = (mask[rowbase + kb + 1] == 0);

        float p0[4], p1[4];
        #pragma unroll
        for (int i = 0; i < 4; i++) {
            float a = s0[i] * 0.125f;
            float c = s1[i] * 0.125f;
            if (mz0) a = -1e9f;
            if (mz1) c = -1e9f;
            float mx = fmaxf(a, c);
            #pragma unroll
            for (int off = 1; off < 16; off <<= 1)
                mx = fmaxf(mx, __shfl_xor_sync(0xffffffffu, mx, off));
            float mnew = fmaxf(mrow[i], mx);
            float al = __expf(mrow[i] - mnew);
            p0[i] = __expf(a - mnew);
            p1[i] = __expf(c - mnew);
            float rs = p0[i] + p1[i];
            #pragma unroll
            for (int off = 1; off < 16; off <<= 1)
                rs += __shfl_xor_sync(0xffffffffu, rs, off);
            lrow[i] = lrow[i] * al + rs;
            mrow[i] = mnew;
            #pragma unroll
            for (int j = 0; j < 4; j++) Oa[i][j] *= al;
        }
        #pragma unroll
        for (int i = 0; i < 4; i++) {
            KP[4*ty + i][2*tx]     = p0[i];
            KP[4*ty + i][2*tx + 1] = p1[i];
        }
        __syncthreads();

        #pragma unroll 8
        for (int kk = 0; kk < 32; kk++) {
            float4 vv = *(const float4*)&Vs[kk][4*tx];
            #pragma unroll
            for (int i = 0; i < 4; i++) {
                float pv = KP[4*ty + i][kk];
                Oa[i][0] = fmaf(pv, vv.x, Oa[i][0]);
                Oa[i][1] = fmaf(pv, vv.y, Oa[i][1]);
                Oa[i][2] = fmaf(pv, vv.z, Oa[i][2]);
                Oa[i][3] = fmaf(pv, vv.w, Oa[i][3]);
            }
        }
        __syncthreads();
    }

    #pragma unroll
    for (int i = 0; i < 4; i++) {
        int q = qt*64 + 4*ty + i;
        float gv = gate[(rowbase + q) * Hsz + h];
        float f = gv / lrow[i];
        size_t obase = (rowbase + q) * Dsz + hoff + 4*tx;
        #pragma unroll
        for (int j = 0; j < 4; j++)
            ctx[obase + j] = Oa[i][j] * f;
    }
}

// ---------------- fused residual add + LayerNorm (one row per block) -----------
__global__ __launch_bounds__(256)
void add_ln_kernel(const float* __restrict__ a, const float* __restrict__ bsrc,
                   const float* __restrict__ g, const float* __restrict__ beta,
                   float* __restrict__ out)
{
    int row = blockIdx.x;
    int tid = threadIdx.x;
    __shared__ float buf[Dsz];
    __shared__ float rsum[8], rsq[8];

    size_t base = (size_t)row * Dsz;
    float ls = 0.0f, lq = 0.0f;
    for (int d = tid; d < Dsz; d += 256) {
        float v = a[base + d] + bsrc[base + d];
        buf[d] = v;
        ls += v; lq += v * v;
    }
    int warp = tid >> 5, lane = tid & 31;
    for (int off = 16; off; off >>= 1) {
        ls += __shfl_xor_sync(0xffffffffu, ls, off);
        lq += __shfl_xor_sync(0xffffffffu, lq, off);
    }
    if (lane == 0) { rsum[warp] = ls; rsq[warp] = lq; }
    __syncthreads();
    float ts = 0.0f, tq = 0.0f;
    #pragma unroll
    for (int w = 0; w < 8; w++) { ts += rsum[w]; tq += rsq[w]; }
    float mean = ts * (1.0f / Dsz);
    float var  = tq * (1.0f / Dsz) - mean * mean;
    float rstd = rsqrtf(var + 1e-5f);
    for (int d = tid; d < Dsz; d += 256)
        out[base + d] = (buf[d] - mean) * rstd * g[d] + beta[d];
}

// ---------------- launch ----------------
static inline void split_launch(const float* src, bf16* h, bf16* l, size_t n)
{
    int n4 = (int)(n / 4);
    split_kernel<<<(n4 + 255) / 256, 256>>>(src, h, l, n4);
}

extern "C" void kernel_launch(void* const* d_in, const int* in_sizes, int n_in,
                              void* d_out, int out_size)
{
    const float* x     = (const float*)d_in[0];
    const float* w_q   = (const float*)d_in[1];
    const float* b_q   = (const float*)d_in[2];
    const float* w_k   = (const float*)d_in[3];
    const float* b_k   = (const float*)d_in[4];
    const float* w_v   = (const float*)d_in[5];
    const float* b_v   = (const float*)d_in[6];
    const float* w_o   = (const float*)d_in[7];
    const float* b_o   = (const float*)d_in[8];
    const float* w_g   = (const float*)d_in[9];
    const float* b_g   = (const float*)d_in[10];
    const float* w1    = (const float*)d_in[11];
    const float* b1    = (const float*)d_in[12];
    const float* w2    = (const float*)d_in[13];
    const float* b2    = (const float*)d_in[14];
    const float* g1    = (const float*)d_in[15];
    const float* beta1 = (const float*)d_in[16];
    const float* g2    = (const float*)d_in[17];
    const float* beta2 = (const float*)d_in[18];
    const int*   mask  = (const int*)  d_in[19];
    float* out = (float*)d_out;

    float *q, *k, *v, *ctx, *tmp, *x1, *ff, *gate;
    cudaGetSymbolAddress((void**)&q,    g_q);
    cudaGetSymbolAddress((void**)&k,    g_k);
    cudaGetSymbolAddress((void**)&v,    g_v);
    cudaGetSymbolAddress((void**)&ctx,  g_ctx);
    cudaGetSymbolAddress((void**)&tmp,  g_tmp);
    cudaGetSymbolAddress((void**)&x1,   g_x1);
    cudaGetSymbolAddress((void**)&ff,   g_ff);
    cudaGetSymbolAddress((void**)&gate, g_gate);

    bf16 *xh,*xl,*ctxh,*ctxl,*x1h,*x1l,*ffh,*ffl;
    bf16 *wqh,*wql,*wkh,*wkl,*wvh,*wvl,*woh,*wol,*w1h,*w1l,*w2h,*w2l;
    cudaGetSymbolAddress((void**)&xh,  g_xh);   cudaGetSymbolAddress((void**)&xl,  g_xl);
    cudaGetSymbolAddress((void**)&ctxh,g_ctxh); cudaGetSymbolAddress((void**)&ctxl,g_ctxl);
    cudaGetSymbolAddress((void**)&x1h, g_x1h);  cudaGetSymbolAddress((void**)&x1l, g_x1l);
    cudaGetSymbolAddress((void**)&ffh, g_ffh);  cudaGetSymbolAddress((void**)&ffl, g_ffl);
    cudaGetSymbolAddress((void**)&wqh, g_wqh);  cudaGetSymbolAddress((void**)&wql, g_wql);
    cudaGetSymbolAddress((void**)&wkh, g_wkh);  cudaGetSymbolAddress((void**)&wkl, g_wkl);
    cudaGetSymbolAddress((void**)&wvh, g_wvh);  cudaGetSymbolAddress((void**)&wvl, g_wvl);
    cudaGetSymbolAddress((void**)&woh, g_woh);  cudaGetSymbolAddress((void**)&wol, g_wol);
    cudaGetSymbolAddress((void**)&w1h, g_w1h);  cudaGetSymbolAddress((void**)&w1l, g_w1l);
    cudaGetSymbolAddress((void**)&w2h, g_w2h);  cudaGetSymbolAddress((void**)&w2l, g_w2l);

    // splits for weights + x
    split_launch(x,   xh,  xl,  (size_t)Msz*Dsz);
    split_launch(w_q, wqh, wql, (size_t)Dsz*Dsz);
    split_launch(w_k, wkh, wkl, (size_t)Dsz*Dsz);
    split_launch(w_v, wvh, wvl, (size_t)Dsz*Dsz);
    split_launch(w_o, woh, wol, (size_t)Dsz*Dsz);
    split_launch(w1,  w1h, w1l, (size_t)Dsz*DFFsz);
    split_launch(w2,  w2h, w2l, (size_t)DFFsz*Dsz);

    dim3 gSq(Dsz/128, Msz/128);      // (8, 64)
    dim3 gF1(DFFsz/128, Msz/128);    // (32, 64)

    gemm_bf16x3_kernel<<<gSq, 256>>>(xh, xl, wqh, wql, b_q, q, Msz, Dsz, Dsz, 0);
    gemm_bf16x3_kernel<<<gSq, 256>>>(xh, xl, wkh, wkl, b_k, k, Msz, Dsz, Dsz, 0);
    gemm_bf16x3_kernel<<<gSq, 256>>>(xh, xl, wvh, wvl, b_v, v, Msz, Dsz, Dsz, 0);
    gate_kernel<<<dim3(Msz/32, 2), 256>>>(x, w_g, b_g, gate);
    flash_kernel<<<dim3(Ssz/64, Hsz, Bsz), 256>>>(q, k, v, gate, mask, ctx);

    split_launch(ctx, ctxh, ctxl, (size_t)Msz*Dsz);
    gemm_bf16x3_kernel<<<gSq, 256>>>(ctxh, ctxl, woh, wol, b_o, tmp, Msz, Dsz, Dsz, 0);
    add_ln_kernel<<<Msz, 256>>>(x, tmp, g1, beta1, x1);

    split_launch(x1, x1h, x1l, (size_t)Msz*Dsz);
    gemm_bf16x3_kernel<<<gF1, 256>>>(x1h, x1l, w1h, w1l, b1, ff, Msz, DFFsz, Dsz, 1);

    split_launch(ff, ffh, ffl, (size_t)Msz*DFFsz);
    gemm_bf16x3_kernel<<<gSq, 256>>>(ffh, ffl, w2h, w2l, b2, tmp, Msz, Dsz, DFFsz, 0);
    add_ln_kernel<<<Msz, 256>>>(x1, tmp, g2, beta2, out);
}

// round 4
// speedup vs baseline: 2.1263x; 1.1824x over previous
#include <cuda_runtime.h>
#include <cuda_bf16.h>
#include <math.h>
#include <cstdint>

// Problem constants
#define Bsz   4
#define Ssz   2048
#define Dsz   1024
#define Hsz   16
#define DKsz  64
#define DFFsz 4096
#define Msz   (Bsz*Ssz)   // 8192 rows

typedef __nv_bfloat16 bf16;

// ---------------- scratch (static device globals; no allocation) ----------------
__device__ float g_tmp [(size_t)Msz*Dsz];   // attn_out, later ff2 out
__device__ float g_x1  [(size_t)Msz*Dsz];
__device__ float g_gate[(size_t)Msz*Hsz];

// bf16 hi/lo pairs
__device__ bf16 g_xh [(size_t)Msz*Dsz],   g_xl [(size_t)Msz*Dsz];
__device__ bf16 g_qh [(size_t)Msz*Dsz],   g_ql [(size_t)Msz*Dsz];
__device__ bf16 g_kh [(size_t)Msz*Dsz],   g_kl [(size_t)Msz*Dsz];
__device__ bf16 g_vh [(size_t)Msz*Dsz],   g_vl [(size_t)Msz*Dsz];
__device__ bf16 g_ctxh[(size_t)Msz*Dsz],  g_ctxl[(size_t)Msz*Dsz];
__device__ bf16 g_x1h[(size_t)Msz*Dsz],   g_x1l[(size_t)Msz*Dsz];
__device__ bf16 g_ffh[(size_t)Msz*DFFsz], g_ffl[(size_t)Msz*DFFsz];
__device__ bf16 g_wqh[(size_t)Dsz*Dsz],   g_wql[(size_t)Dsz*Dsz];
__device__ bf16 g_wkh[(size_t)Dsz*Dsz],   g_wkl[(size_t)Dsz*Dsz];
__device__ bf16 g_wvh[(size_t)Dsz*Dsz],   g_wvl[(size_t)Dsz*Dsz];
__device__ bf16 g_woh[(size_t)Dsz*Dsz],   g_wol[(size_t)Dsz*Dsz];
__device__ bf16 g_w1h[(size_t)Dsz*DFFsz], g_w1l[(size_t)Dsz*DFFsz];
__device__ bf16 g_w2h[(size_t)DFFsz*Dsz], g_w2l[(size_t)DFFsz*Dsz];

// ---------------- small helpers ----------------
__device__ __forceinline__ void cp16(uint32_t dst, const void* src) {
    asm volatile("cp.async.ca.shared.global [%0], [%1], 16;\n" :: "r"(dst), "l"(src));
}
__device__ __forceinline__ void cp_commit() {
    asm volatile("cp.async.commit_group;\n");
}
__device__ __forceinline__ void cp_wait0() {
    asm volatile("cp.async.wait_group 0;\n");
}
__device__ __forceinline__ void ldsm4(uint32_t* r, uint32_t addr) {
    asm volatile("ldmatrix.sync.aligned.m8n8.x4.shared.b16 {%0,%1,%2,%3}, [%4];"
                 : "=r"(r[0]), "=r"(r[1]), "=r"(r[2]), "=r"(r[3]) : "r"(addr));
}
__device__ __forceinline__ void ldsm4t(uint32_t& r0, uint32_t& r1,
                                       uint32_t& r2, uint32_t& r3, uint32_t addr) {
    asm volatile("ldmatrix.sync.aligned.m8n8.x4.trans.shared.b16 {%0,%1,%2,%3}, [%4];"
                 : "=r"(r0), "=r"(r1), "=r"(r2), "=r"(r3) : "r"(addr));
}
__device__ __forceinline__ void mma16816(float* ac, const uint32_t* a,
                                         uint32_t b0, uint32_t b1) {
    asm volatile(
        "mma.sync.aligned.m16n8k16.row.col.f32.bf16.bf16.f32 "
        "{%0,%1,%2,%3},{%4,%5,%6,%7},{%8,%9},{%0,%1,%2,%3};"
        : "+f"(ac[0]), "+f"(ac[1]), "+f"(ac[2]), "+f"(ac[3])
        : "r"(a[0]), "r"(a[1]), "r"(a[2]), "r"(a[3]), "r"(b0), "r"(b1));
}
// pack two floats -> bf16x2 (hi) + residual bf16x2 (lo), as u32 regs
__device__ __forceinline__ void pack_pair(float a, float b, uint32_t& hi, uint32_t& lo) {
    bf16 ha = __float2bfloat16(a), hb = __float2bfloat16(b);
    bf16 la = __float2bfloat16(a - __bfloat162float(ha));
    bf16 lb = __float2bfloat16(b - __bfloat162float(hb));
    __nv_bfloat162 th = __halves2bfloat162(ha, hb);
    __nv_bfloat162 tl = __halves2bfloat162(la, lb);
    hi = *(uint32_t*)&th; lo = *(uint32_t*)&tl;
}

// ---------------- fp32 -> bf16 hi/lo split ----------------
__global__ __launch_bounds__(256)
void split_kernel(const float* __restrict__ in, bf16* __restrict__ hi,
                  bf16* __restrict__ lo, int n4)
{
    int i = blockIdx.x * 256 + threadIdx.x;
    if (i >= n4) return;
    float4 v = ((const float4*)in)[i];
    uint32_t h0, l0, h1, l1;
    pack_pair(v.x, v.y, h0, l0);
    pack_pair(v.z, v.w, h1, l1);
    uint32_t* hp = (uint32_t*)hi;
    uint32_t* lp = (uint32_t*)lo;
    hp[2*i] = h0; hp[2*i+1] = h1;
    lp[2*i] = l0; lp[2*i+1] = l1;
}

// ---------------- bf16x3 tensor-core GEMM ----------------
// acc = Ah*Wh + Al*Wh + Ah*Wl. mode bits: 1=GELU, 2=write fp32 C, 4=write bf16 Ch/Cl
#define APAD 24   // 16 + 8 bf16 pad
#define WPAD 136  // 128 + 8 pad

__global__ __launch_bounds__(256)
void gemm_bf16x3_kernel(const bf16* __restrict__ Ah, const bf16* __restrict__ Al,
                        const bf16* __restrict__ Wh, const bf16* __restrict__ Wl,
                        const float* __restrict__ bias, float* __restrict__ C,
                        bf16* __restrict__ Ch, bf16* __restrict__ Cl,
                        int M, int N, int K, int mode)
{
    __shared__ __align__(16) bf16 sAh[2][128][APAD];
    __shared__ __align__(16) bf16 sAl[2][128][APAD];
    __shared__ __align__(16) bf16 sWh[2][16][WPAD];
    __shared__ __align__(16) bf16 sWl[2][16][WPAD];

    const int tid = threadIdx.x;
    const int row0 = blockIdx.y * 128, col0 = blockIdx.x * 128;

    const char* pAh = (const char*)(Ah + (size_t)(row0 + (tid>>1)) * K + (tid&1)*8);
    const char* pAl = (const char*)(Al + (size_t)(row0 + (tid>>1)) * K + (tid&1)*8);
    const char* pWh = (const char*)(Wh + (size_t)(tid>>4) * N + col0 + (tid&15)*8);
    const char* pWl = (const char*)(Wl + (size_t)(tid>>4) * N + col0 + (tid&15)*8);

    const uint32_t aAh = (uint32_t)__cvta_generic_to_shared(&sAh[0][0][0]);
    const uint32_t aAl = (uint32_t)__cvta_generic_to_shared(&sAl[0][0][0]);
    const uint32_t aWh = (uint32_t)__cvta_generic_to_shared(&sWh[0][0][0]);
    const uint32_t aWl = (uint32_t)__cvta_generic_to_shared(&sWl[0][0][0]);
    const uint32_t SA = 128*APAD*2, SW = 16*WPAD*2;
    const uint32_t dA = ((tid>>1)*APAD + (tid&1)*8) * 2;
    const uint32_t dW = ((tid>>4)*WPAD + (tid&15)*8) * 2;

    float acc[4][4][4];
    #pragma unroll
    for (int i = 0; i < 4; i++)
        #pragma unroll
        for (int j = 0; j < 4; j++)
            #pragma unroll
            for (int t = 0; t < 4; t++) acc[i][j][t] = 0.0f;

    const int wid = tid >> 5, lane = tid & 31;
    const int wm = wid & 1;
    const int wn = wid >> 1;
    const int lrow = lane & 15, lk = (lane >> 4) * 8;
    const uint32_t offA0 = (uint32_t)(((wm*64 + lrow) * APAD + lk) * 2);
    const uint32_t offB0 = (uint32_t)(((lane & 15) * WPAD + wn*32 + (lane>>4)*8) * 2);

    const int nit = K / 16;

    cp16(aAh + dA, pAh);
    cp16(aAl + dA, pAl);
    cp16(aWh + dW, pWh);
    cp16(aWl + dW, pWl);
    cp_commit();

    for (int it = 0; it < nit; ++it) {
        cp_wait0();
        __syncthreads();
        if (it + 1 < nit) {
            uint32_t st = (uint32_t)((it + 1) & 1);
            size_t ka = (size_t)(it + 1) * 16 * 2;
            size_t kw = (size_t)(it + 1) * 16 * (size_t)N * 2;
            cp16(aAh + st*SA + dA, pAh + ka);
            cp16(aAl + st*SA + dA, pAl + ka);
            cp16(aWh + st*SW + dW, pWh + kw);
            cp16(aWl + st*SW + dW, pWl + kw);
            cp_commit();
        }
        const uint32_t s = (uint32_t)(it & 1);

        uint32_t afh[4][4], afl[4][4];
        #pragma unroll
        for (int mi = 0; mi < 4; mi++)
            ldsm4(afh[mi], aAh + s*SA + offA0 + mi*16*APAD*2);
        #pragma unroll
        for (int mi = 0; mi < 4; mi++)
            ldsm4(afl[mi], aAl + s*SA + offA0 + mi*16*APAD*2);

        uint32_t bfr[4][2];
        #pragma unroll
        for (int ng = 0; ng < 2; ng++)
            ldsm4t(bfr[2*ng][0], bfr[2*ng][1], bfr[2*ng+1][0], bfr[2*ng+1][1],
                   aWh + s*SW + offB0 + (uint32_t)(ng*16*2));
        #pragma unroll
        for (int mi = 0; mi < 4; mi++)
            #pragma unroll
            for (int ni = 0; ni < 4; ni++) {
                mma16816(acc[mi][ni], afh[mi], bfr[ni][0], bfr[ni][1]);
                mma16816(acc[mi][ni], afl[mi], bfr[ni][0], bfr[ni][1]);
            }
        #pragma unroll
        for (int ng = 0; ng < 2; ng++)
            ldsm4t(bfr[2*ng][0], bfr[2*ng][1], bfr[2*ng+1][0], bfr[2*ng+1][1],
                   aWl + s*SW + offB0 + (uint32_t)(ng*16*2));
        #pragma unroll
        for (int mi = 0; mi < 4; mi++)
            #pragma unroll
            for (int ni = 0; ni < 4; ni++)
                mma16816(acc[mi][ni], afh[mi], bfr[ni][0], bfr[ni][1]);
    }

    // epilogue
    #pragma unroll
    for (int mi = 0; mi < 4; mi++) {
        #pragma unroll
        for (int ni = 0; ni < 4; ni++) {
            int c = col0 + wn*32 + ni*8 + (lane & 3)*2;
            float bx = bias[c], by = bias[c + 1];
            #pragma unroll
            for (int rh = 0; rh < 2; rh++) {
                size_t r = (size_t)(row0 + wm*64 + mi*16 + (lane >> 2) + rh*8);
                float v0 = acc[mi][ni][2*rh]     + bx;
                float v1 = acc[mi][ni][2*rh + 1] + by;
                if (mode & 1) {
                    v0 = 0.5f * v0 * (1.0f + erff(v0 * 0.70710678118654752f));
                    v1 = 0.5f * v1 * (1.0f + erff(v1 * 0.70710678118654752f));
                }
                if (mode & 2) {
                    float2 o; o.x = v0; o.y = v1;
                    *(float2*)&C[r * N + c] = o;
                }
                if (mode & 4) {
                    uint32_t hp, lp;
                    pack_pair(v0, v1, hp, lp);
                    *(uint32_t*)&Ch[r * N + c] = hp;
                    *(uint32_t*)&Cl[r * N + c] = lp;
                }
            }
        }
    }
}

// ---------------- sigmoid gate ----------------------
__global__ __launch_bounds__(256)
void gate_kernel(const float* __restrict__ x, const float* __restrict__ wg,
                 const float* __restrict__ bg, float* __restrict__ gate)
{
    __shared__ float wgs[Dsz][8];
    int hg = blockIdx.y;
    int tid = threadIdx.x;
    for (int idx = tid; idx < Dsz*8; idx += 256)
        wgs[idx >> 3][idx & 7] = wg[(idx >> 3) * Hsz + hg*8 + (idx & 7)];
    __syncthreads();

    int h = tid & 7, r = tid >> 3;
    int m = blockIdx.x * 32 + r;
    const float4* xr = (const float4*)(x + (size_t)m * Dsz);
    float s = 0.0f;
    #pragma unroll 4
    for (int d4 = 0; d4 < Dsz/4; d4++) {
        float4 xv = xr[d4];
        s = fmaf(xv.x, wgs[d4*4 + 0][h], s);
        s = fmaf(xv.y, wgs[d4*4 + 1][h], s);
        s = fmaf(xv.z, wgs[d4*4 + 2][h], s);
        s = fmaf(xv.w, wgs[d4*4 + 3][h], s);
    }
    s += bg[hg*8 + h];
    gate[(size_t)m * Hsz + hg*8 + h] = 1.0f / (1.0f + __expf(-s));
}

// ---------------- tensor-core flash attention ----------------
// Block: 128 threads (4 warps), q-tile 64 (16 q/warp), k-tile 64, head dim 64.
// S = Qh*Kh + Ql*Kh + Qh*Kl ; P@V = Ph*Vh + Ph*Vl + Pl*Vh.
#define FPAD 72
#define KV_STRIDE (64*FPAD)            // elems per [64][72] buffer
#define STAGE_ELEMS (4*KV_STRIDE)      // Kh,Kl,Vh,Vl
#define FLASH_SMEM (2*STAGE_ELEMS*2 + 2*64*4)

__global__ __launch_bounds__(128, 3)
void flash_tc_kernel(const bf16* __restrict__ Qh, const bf16* __restrict__ Ql,
                     const bf16* __restrict__ Kh, const bf16* __restrict__ Kl,
                     const bf16* __restrict__ Vh, const bf16* __restrict__ Vl,
                     const float* __restrict__ gate, const int* __restrict__ mask,
                     bf16* __restrict__ Ch, bf16* __restrict__ Cl)
{
    extern __shared__ __align__(16) char dynsmem[];
    int* smsk = (int*)(dynsmem + (size_t)2*STAGE_ELEMS*2);

    const int tid = threadIdx.x, lane = tid & 31, warp = tid >> 5;
    const int qt = blockIdx.x, h = blockIdx.y, b = blockIdx.z;
    const size_t rowbase = (size_t)b * Ssz;
    const size_t hoff = (size_t)h * DKsz;

    const uint32_t sbase = (uint32_t)__cvta_generic_to_shared(dynsmem);
    const uint32_t mbase = (uint32_t)__cvta_generic_to_shared(smsk);

    // ---- stage Q (hi into buf0, lo into buf1 of stage 0), extract fragments ----
    {
        int r = tid >> 1;
        size_t gq = (rowbase + qt*64 + r) * Dsz + hoff;
        #pragma unroll
        for (int j = 0; j < 4; j++) {
            int c8 = (tid & 1)*4 + j;
            uint32_t dof = (uint32_t)((r*FPAD + c8*8)*2);
            cp16(sbase + 0*KV_STRIDE*2 + dof, Qh + gq + c8*8);
            cp16(sbase + 1*KV_STRIDE*2 + dof, Ql + gq + c8*8);
        }
        cp_commit(); cp_wait0();
    }
    __syncthreads();

    uint32_t qfh[4][4], qfl[4][4];
    {
        uint32_t arow = (uint32_t)((warp*16 + (lane&15))*FPAD*2);
        #pragma unroll
        for (int ks = 0; ks < 4; ks++) {
            uint32_t acol = (uint32_t)((16*ks + (lane>>4)*8)*2);
            ldsm4(qfh[ks], sbase + 0*KV_STRIDE*2 + arow + acol);
            ldsm4(qfl[ks], sbase + 1*KV_STRIDE*2 + arow + acol);
        }
    }
    __syncthreads();

    float oacc[8][4];
    #pragma unroll
    for (int i = 0; i < 8; i++)
        #pragma unroll
        for (int j = 0; j < 4; j++) oacc[i][j] = 0.0f;
    float m0 = -1e30f, m1 = -1e30f, l0 = 0.0f, l1 = 0.0f;

    // K/V tile loader
    const int r_ld = tid >> 1;
    const int cbase = (tid & 1)*4;

    // prologue tile 0
    {
        size_t g = (rowbase + r_ld) * Dsz + hoff;
        #pragma unroll
        for (int j = 0; j < 4; j++) {
            int c8 = cbase + j;
            uint32_t dof = (uint32_t)((r_ld*FPAD + c8*8)*2);
            cp16(sbase + 0*KV_STRIDE*2 + dof, Kh + g + c8*8);
            cp16(sbase + 1*KV_STRIDE*2 + dof, Kl + g + c8*8);
            cp16(sbase + 2*KV_STRIDE*2 + dof, Vh + g + c8*8);
            cp16(sbase + 3*KV_STRIDE*2 + dof, Vl + g + c8*8);
        }
        if (tid < 16) cp16(mbase + tid*16, mask + rowbase + tid*4);
        cp_commit();
    }

    const int col0 = 2*(lane & 3);

    for (int kt = 0; kt < Ssz/64; kt++) {
        cp_wait0();
        __syncthreads();
        if (kt + 1 < Ssz/64) {
            int st = (kt + 1) & 1;
            size_t g = (rowbase + (kt+1)*64 + r_ld) * Dsz + hoff;
            uint32_t sb = sbase + (uint32_t)(st*STAGE_ELEMS*2);
            #pragma unroll
            for (int j = 0; j < 4; j++) {
                int c8 = cbase + j;
                uint32_t dof = (uint32_t)((r_ld*FPAD + c8*8)*2);
                cp16(sb + 0*KV_STRIDE*2 + dof, Kh + g + c8*8);
                cp16(sb + 1*KV_STRIDE*2 + dof, Kl + g + c8*8);
                cp16(sb + 2*KV_STRIDE*2 + dof, Vh + g + c8*8);
                cp16(sb + 3*KV_STRIDE*2 + dof, Vl + g + c8*8);
            }
            if (tid < 16) cp16(mbase + st*256 + tid*16, mask + rowbase + (kt+1)*64 + tid*4);
            cp_commit();
        }
        const int st = kt & 1;
        const uint32_t kb = sbase + (uint32_t)(st*STAGE_ELEMS*2);

        // ---- S = Q K^T ----
        float sc[8][4];
        #pragma unroll
        for (int i = 0; i < 8; i++)
            #pragma unroll
            for (int j = 0; j < 4; j++) sc[i][j] = 0.0f;

        const uint32_t brow = (uint32_t)(((lane&7) + ((lane>>1)&8)) * FPAD * 2);
        const uint32_t bcol = (uint32_t)((lane & 8) * 2);
        #pragma unroll
        for (int ng = 0; ng < 4; ng++) {
            #pragma unroll
            for (int ks = 0; ks < 4; ks++) {
                uint32_t ba = kb + brow + (uint32_t)(16*ng*FPAD*2) + bcol + (uint32_t)(16*ks*2);
                uint32_t bh4[4], bl4[4];
                ldsm4(bh4, ba);
                ldsm4(bl4, ba + KV_STRIDE*2);
                mma16816(sc[2*ng],   qfh[ks], bh4[0], bh4[1]);
                mma16816(sc[2*ng+1], qfh[ks], bh4[2], bh4[3]);
                mma16816(sc[2*ng],   qfl[ks], bh4[0], bh4[1]);
                mma16816(sc[2*ng+1], qfl[ks], bh4[2], bh4[3]);
                mma16816(sc[2*ng],   qfh[ks], bl4[0], bl4[1]);
                mma16816(sc[2*ng+1], qfh[ks], bl4[2], bl4[3]);
            }
        }

        // ---- online softmax ----
        const int* mk = smsk + st*64;
        float mx0 = -1e30f, mx1 = -1e30f;
        #pragma unroll
        for (int ni = 0; ni < 8; ni++) {
            int c = 8*ni + col0;
            bool z0 = (mk[c] == 0), z1 = (mk[c+1] == 0);
            sc[ni][0] = z0 ? -1e9f : sc[ni][0]*0.125f;
            sc[ni][1] = z1 ? -1e9f : sc[ni][1]*0.125f;
            sc[ni][2] = z0 ? -1e9f : sc[ni][2]*0.125f;
            sc[ni][3] = z1 ? -1e9f : sc[ni][3]*0.125f;
            mx0 = fmaxf(mx0, fmaxf(sc[ni][0], sc[ni][1]));
            mx1 = fmaxf(mx1, fmaxf(sc[ni][2], sc[ni][3]));
        }
        mx0 = fmaxf(mx0, __shfl_xor_sync(0xffffffffu, mx0, 1));
        mx0 = fmaxf(mx0, __shfl_xor_sync(0xffffffffu, mx0, 2));
        mx1 = fmaxf(mx1, __shfl_xor_sync(0xffffffffu, mx1, 1));
        mx1 = fmaxf(mx1, __shfl_xor_sync(0xffffffffu, mx1, 2));
        float mn0 = fmaxf(m0, mx0), mn1 = fmaxf(m1, mx1);
        float al0 = __expf(m0 - mn0), al1 = __expf(m1 - mn1);
        float rs0 = 0.0f, rs1 = 0.0f;
        #pragma unroll
        for (int ni = 0; ni < 8; ni++) {
            sc[ni][0] = __expf(sc[ni][0] - mn0);
            sc[ni][1] = __expf(sc[ni][1] - mn0);
            sc[ni][2] = __expf(sc[ni][2] - mn1);
            sc[ni][3] = __expf(sc[ni][3] - mn1);
            rs0 += sc[ni][0] + sc[ni][1];
            rs1 += sc[ni][2] + sc[ni][3];
        }
        rs0 += __shfl_xor_sync(0xffffffffu, rs0, 1);
        rs0 += __shfl_xor_sync(0xffffffffu, rs0, 2);
        rs1 += __shfl_xor_sync(0xffffffffu, rs1, 1);
        rs1 += __shfl_xor_sync(0xffffffffu, rs1, 2);
        l0 = l0*al0 + rs0; l1 = l1*al1 + rs1;
        m0 = mn0; m1 = mn1;
        #pragma unroll
        for (int ni = 0; ni < 8; ni++) {
            oacc[ni][0] *= al0; oacc[ni][1] *= al0;
            oacc[ni][2] *= al1; oacc[ni][3] *= al1;
        }

        // ---- O += P V ----
        const uint32_t vrow0 = (uint32_t)((lane&15)*FPAD*2);
        const uint32_t vcol0 = (uint32_t)(((lane>>4)*8)*2);
        #pragma unroll
        for (int ki = 0; ki < 4; ki++) {
            uint32_t ph[4], pl[4];
            pack_pair(sc[2*ki][0],   sc[2*ki][1],   ph[0], pl[0]);
            pack_pair(sc[2*ki][2],   sc[2*ki][3],   ph[1], pl[1]);
            pack_pair(sc[2*ki+1][0], sc[2*ki+1][1], ph[2], pl[2]);
            pack_pair(sc[2*ki+1][2], sc[2*ki+1][3], ph[3], pl[3]);
            uint32_t va0 = kb + 2*KV_STRIDE*2 + vrow0 + (uint32_t)(16*ki*FPAD*2) + vcol0;
            #pragma unroll
            for (int ngd = 0; ngd < 4; ngd++) {
                uint32_t vh4[4], vl4[4];
                ldsm4t(vh4[0], vh4[1], vh4[2], vh4[3], va0 + (uint32_t)(16*ngd*2));
                ldsm4t(vl4[0], vl4[1], vl4[2], vl4[3], va0 + KV_STRIDE*2 + (uint32_t)(16*ngd*2));
                mma16816(oacc[2*ngd],   ph, vh4[0], vh4[1]);
                mma16816(oacc[2*ngd+1], ph, vh4[2], vh4[3]);
                mma16816(oacc[2*ngd],   ph, vl4[0], vl4[1]);
                mma16816(oacc[2*ngd+1], ph, vl4[2], vl4[3]);
                mma16816(oacc[2*ngd],   pl, vh4[0], vh4[1]);
                mma16816(oacc[2*ngd+1], pl, vh4[2], vh4[3]);
            }
        }
    }

    // ---- epilogue: scale by gate/l, write ctx hi/lo ----
    int q0 = qt*64 + warp*16 + (lane >> 2);
    float f0 = gate[(rowbase + q0)*Hsz + h] / l0;
    float f1 = gate[(rowbase + q0 + 8)*Hsz + h] / l1;
    #pragma unroll
    for (int ni = 0; ni < 8; ni++) {
        size_t o0 = (rowbase + q0) * Dsz + hoff + 8*ni + col0;
        size_t o1 = o0 + (size_t)8 * Dsz;
        uint32_t hp, lp;
        pack_pair(oacc[ni][0]*f0, oacc[ni][1]*f0, hp, lp);
        *(uint32_t*)&Ch[o0] = hp;
        *(uint32_t*)&Cl[o0] = lp;
        pack_pair(oacc[ni][2]*f1, oacc[ni][3]*f1, hp, lp);
        *(uint32_t*)&Ch[o1] = hp;
        *(uint32_t*)&Cl[o1] = lp;
    }
}

// ---------------- fused residual add + LayerNorm (+ optional bf16 split out) ----
__global__ __launch_bounds__(256)
void add_ln_kernel(const float* __restrict__ a, const float* __restrict__ bsrc,
                   const float* __restrict__ g, const float* __restrict__ beta,
                   float* __restrict__ out, bf16* __restrict__ oh, bf16* __restrict__ ol)
{
    int row = blockIdx.x;
    int tid = threadIdx.x;
    __shared__ float buf[Dsz];
    __shared__ float rsum[8], rsq[8];

    size_t base = (size_t)row * Dsz;
    float ls = 0.0f, lq = 0.0f;
    for (int d = tid; d < Dsz; d += 256) {
        float v = a[base + d] + bsrc[base + d];
        buf[d] = v;
        ls += v; lq += v * v;
    }
    int warp = tid >> 5, lane = tid & 31;
    for (int off = 16; off; off >>= 1) {
        ls += __shfl_xor_sync(0xffffffffu, ls, off);
        lq += __shfl_xor_sync(0xffffffffu, lq, off);
    }
    if (lane == 0) { rsum[warp] = ls; rsq[warp] = lq; }
    __syncthreads();
    float ts = 0.0f, tq = 0.0f;
    #pragma unroll
    for (int w = 0; w < 8; w++) { ts += rsum[w]; tq += rsq[w]; }
    float mean = ts * (1.0f / Dsz);
    float var  = tq * (1.0f / Dsz) - mean * mean;
    float rstd = rsqrtf(var + 1e-5f);
    for (int d = tid; d < Dsz; d += 256) {
        float v = (buf[d] - mean) * rstd * g[d] + beta[d];
        out[base + d] = v;
        if (oh) {
            bf16 hv = __float2bfloat16(v);
            oh[base + d] = hv;
            ol[base + d] = __float2bfloat16(v - __bfloat162float(hv));
        }
    }
}

// ---------------- launch ----------------
static inline void split_launch(const float* src, bf16* h, bf16* l, size_t n)
{
    int n4 = (int)(n / 4);
    split_kernel<<<(n4 + 255) / 256, 256>>>(src, h, l, n4);
}

extern "C" void kernel_launch(void* const* d_in, const int* in_sizes, int n_in,
                              void* d_out, int out_size)
{
    const float* x     = (const float*)d_in[0];
    const float* w_q   = (const float*)d_in[1];
    const float* b_q   = (const float*)d_in[2];
    const float* w_k   = (const float*)d_in[3];
    const float* b_k   = (const float*)d_in[4];
    const float* w_v   = (const float*)d_in[5];
    const float* b_v   = (const float*)d_in[6];
    const float* w_o   = (const float*)d_in[7];
    const float* b_o   = (const float*)d_in[8];
    const float* w_g   = (const float*)d_in[9];
    const float* b_g   = (const float*)d_in[10];
    const float* w1    = (const float*)d_in[11];
    const float* b1    = (const float*)d_in[12];
    const float* w2    = (const float*)d_in[13];
    const float* b2    = (const float*)d_in[14];
    const float* g1    = (const float*)d_in[15];
    const float* beta1 = (const float*)d_in[16];
    const float* g2    = (const float*)d_in[17];
    const float* beta2 = (const float*)d_in[18];
    const int*   mask  = (const int*)  d_in[19];
    float* out = (float*)d_out;

    float *tmp, *x1, *gate;
    cudaGetSymbolAddress((void**)&tmp,  g_tmp);
    cudaGetSymbolAddress((void**)&x1,   g_x1);
    cudaGetSymbolAddress((void**)&gate, g_gate);

    bf16 *xh,*xl,*qh,*ql,*kh,*kl,*vh,*vl,*ctxh,*ctxl,*x1h,*x1l,*ffh,*ffl;
    bf16 *wqh,*wql,*wkh,*wkl,*wvh,*wvl,*woh,*wol,*w1h,*w1l,*w2h,*w2l;
    cudaGetSymbolAddress((void**)&xh,  g_xh);   cudaGetSymbolAddress((void**)&xl,  g_xl);
    cudaGetSymbolAddress((void**)&qh,  g_qh);   cudaGetSymbolAddress((void**)&ql,  g_ql);
    cudaGetSymbolAddress((void**)&kh,  g_kh);   cudaGetSymbolAddress((void**)&kl,  g_kl);
    cudaGetSymbolAddress((void**)&vh,  g_vh);   cudaGetSymbolAddress((void**)&vl,  g_vl);
    cudaGetSymbolAddress((void**)&ctxh,g_ctxh); cudaGetSymbolAddress((void**)&ctxl,g_ctxl);
    cudaGetSymbolAddress((void**)&x1h, g_x1h);  cudaGetSymbolAddress((void**)&x1l, g_x1l);
    cudaGetSymbolAddress((void**)&ffh, g_ffh);  cudaGetSymbolAddress((void**)&ffl, g_ffl);
    cudaGetSymbolAddress((void**)&wqh, g_wqh);  cudaGetSymbolAddress((void**)&wql, g_wql);
    cudaGetSymbolAddress((void**)&wkh, g_wkh);  cudaGetSymbolAddress((void**)&wkl, g_wkl);
    cudaGetSymbolAddress((void**)&wvh, g_wvh);  cudaGetSymbolAddress((void**)&wvl, g_wvl);
    cudaGetSymbolAddress((void**)&woh, g_woh);  cudaGetSymbolAddress((void**)&wol, g_wol);
    cudaGetSymbolAddress((void**)&w1h, g_w1h);  cudaGetSymbolAddress((void**)&w1l, g_w1l);
    cudaGetSymbolAddress((void**)&w2h, g_w2h);  cudaGetSymbolAddress((void**)&w2l, g_w2l);

    cudaFuncSetAttribute(flash_tc_kernel,
                         cudaFuncAttributeMaxDynamicSharedMemorySize, FLASH_SMEM);

    // splits for weights + x
    split_launch(x,   xh,  xl,  (size_t)Msz*Dsz);
    split_launch(w_q, wqh, wql, (size_t)Dsz*Dsz);
    split_launch(w_k, wkh, wkl, (size_t)Dsz*Dsz);
    split_launch(w_v, wvh, wvl, (size_t)Dsz*Dsz);
    split_launch(w_o, woh, wol, (size_t)Dsz*Dsz);
    split_launch(w1,  w1h, w1l, (size_t)Dsz*DFFsz);
    split_launch(w2,  w2h, w2l, (size_t)DFFsz*Dsz);

    dim3 gSq(Dsz/128, Msz/128);      // (8, 64)
    dim3 gF1(DFFsz/128, Msz/128);    // (32, 64)

    // QKV: bf16 hi/lo outputs only (mode 4)
    gemm_bf16x3_kernel<<<gSq, 256>>>(xh, xl, wqh, wql, b_q, nullptr, qh, ql, Msz, Dsz, Dsz, 4);
    gemm_bf16x3_kernel<<<gSq, 256>>>(xh, xl, wkh, wkl, b_k, nullptr, kh, kl, Msz, Dsz, Dsz, 4);
    gemm_bf16x3_kernel<<<gSq, 256>>>(xh, xl, wvh, wvl, b_v, nullptr, vh, vl, Msz, Dsz, Dsz, 4);
    gate_kernel<<<dim3(Msz/32, 2), 256>>>(x, w_g, b_g, gate);

    flash_tc_kernel<<<dim3(Ssz/64, Hsz, Bsz), 128, FLASH_SMEM>>>(
        qh, ql, kh, kl, vh, vl, gate, mask, ctxh, ctxl);

    // O-proj: fp32 out (mode 2)
    gemm_bf16x3_kernel<<<gSq, 256>>>(ctxh, ctxl, woh, wol, b_o, tmp, nullptr, nullptr, Msz, Dsz, Dsz, 2);
    add_ln_kernel<<<Msz, 256>>>(x, tmp, g1, beta1, x1, x1h, x1l);

    // FF1: GELU + bf16 hi/lo (mode 5)
    gemm_bf16x3_kernel<<<gF1, 256>>>(x1h, x1l, w1h, w1l, b1, nullptr, ffh, ffl, Msz, DFFsz, Dsz, 5);
    // FF2: fp32 out (mode 2)
    gemm_bf16x3_kernel<<<gSq, 256>>>(ffh, ffl, w2h, w2l, b2, tmp, nullptr, nullptr, Msz, Dsz, DFFsz, 2);
    add_ln_kernel<<<Msz, 256>>>(x1, tmp, g2, beta2, out, nullptr, nullptr);
}

// round 6
// speedup vs baseline: 2.2501x; 1.0582x over previous
#include <cuda_runtime.h>
#include <cuda_bf16.h>
#include <math.h>
#include <cstdint>

// Problem constants
#define Bsz   4
#define Ssz   2048
#define Dsz   1024
#define Hsz   16
#define DKsz  64
#define DFFsz 4096
#define Msz   (Bsz*Ssz)   // 8192 rows

typedef __nv_bfloat16 bf16;

// ---------------- scratch (static device globals; no allocation) ----------------
__device__ float g_tmp [(size_t)Msz*Dsz];   // attn_out, later ff2 out
__device__ float g_x1  [(size_t)Msz*Dsz];
__device__ float g_gate[(size_t)Msz*Hsz];

// bf16 hi/lo pairs
__device__ bf16 g_xh [(size_t)Msz*Dsz],   g_xl [(size_t)Msz*Dsz];
__device__ bf16 g_qh [(size_t)Msz*Dsz],   g_ql [(size_t)Msz*Dsz];
__device__ bf16 g_kh [(size_t)Msz*Dsz],   g_kl [(size_t)Msz*Dsz];
__device__ bf16 g_vh [(size_t)Msz*Dsz],   g_vl [(size_t)Msz*Dsz];
__device__ bf16 g_ctxh[(size_t)Msz*Dsz],  g_ctxl[(size_t)Msz*Dsz];
__device__ bf16 g_x1h[(size_t)Msz*Dsz],   g_x1l[(size_t)Msz*Dsz];
__device__ bf16 g_ffh[(size_t)Msz*DFFsz], g_ffl[(size_t)Msz*DFFsz];
__device__ bf16 g_wqh[(size_t)Dsz*Dsz],   g_wql[(size_t)Dsz*Dsz];
__device__ bf16 g_wkh[(size_t)Dsz*Dsz],   g_wkl[(size_t)Dsz*Dsz];
__device__ bf16 g_wvh[(size_t)Dsz*Dsz],   g_wvl[(size_t)Dsz*Dsz];
__device__ bf16 g_woh[(size_t)Dsz*Dsz],   g_wol[(size_t)Dsz*Dsz];
__device__ bf16 g_w1h[(size_t)Dsz*DFFsz], g_w1l[(size_t)Dsz*DFFsz];
__device__ bf16 g_w2h[(size_t)DFFsz*Dsz], g_w2l[(size_t)DFFsz*Dsz];

// ---------------- small helpers ----------------
__device__ __forceinline__ void cp16(uint32_t dst, const void* src) {
    asm volatile("cp.async.ca.shared.global [%0], [%1], 16;\n" :: "r"(dst), "l"(src));
}
__device__ __forceinline__ void cp_commit() {
    asm volatile("cp.async.commit_group;\n");
}
__device__ __forceinline__ void cp_wait0() {
    asm volatile("cp.async.wait_group 0;\n");
}
__device__ __forceinline__ void cp_wait1() {
    asm volatile("cp.async.wait_group 1;\n");
}
__device__ __forceinline__ void ldsm4(uint32_t* r, uint32_t addr) {
    asm volatile("ldmatrix.sync.aligned.m8n8.x4.shared.b16 {%0,%1,%2,%3}, [%4];"
                 : "=r"(r[0]), "=r"(r[1]), "=r"(r[2]), "=r"(r[3]) : "r"(addr));
}
__device__ __forceinline__ void ldsm4t(uint32_t& r0, uint32_t& r1,
                                       uint32_t& r2, uint32_t& r3, uint32_t addr) {
    asm volatile("ldmatrix.sync.aligned.m8n8.x4.trans.shared.b16 {%0,%1,%2,%3}, [%4];"
                 : "=r"(r0), "=r"(r1), "=r"(r2), "=r"(r3) : "r"(addr));
}
__device__ __forceinline__ void mma16816(float* ac, const uint32_t* a,
                                         uint32_t b0, uint32_t b1) {
    asm volatile(
        "mma.sync.aligned.m16n8k16.row.col.f32.bf16.bf16.f32 "
        "{%0,%1,%2,%3},{%4,%5,%6,%7},{%8,%9},{%0,%1,%2,%3};"
        : "+f"(ac[0]), "+f"(ac[1]), "+f"(ac[2]), "+f"(ac[3])
        : "r"(a[0]), "r"(a[1]), "r"(a[2]), "r"(a[3]), "r"(b0), "r"(b1));
}
__device__ __forceinline__ void pack_pair(float a, float b, uint32_t& hi, uint32_t& lo) {
    bf16 ha = __float2bfloat16(a), hb = __float2bfloat16(b);
    bf16 la = __float2bfloat16(a - __bfloat162float(ha));
    bf16 lb = __float2bfloat16(b - __bfloat162float(hb));
    __nv_bfloat162 th = __halves2bfloat162(ha, hb);
    __nv_bfloat162 tl = __halves2bfloat162(la, lb);
    hi = *(uint32_t*)&th; lo = *(uint32_t*)&tl;
}

// ---------------- fp32 -> bf16 hi/lo split ----------------
__global__ __launch_bounds__(256)
void split_kernel(const float* __restrict__ in, bf16* __restrict__ hi,
                  bf16* __restrict__ lo, int n4)
{
    int i = blockIdx.x * 256 + threadIdx.x;
    if (i >= n4) return;
    float4 v = ((const float4*)in)[i];
    uint32_t h0, l0, h1, l1;
    pack_pair(v.x, v.y, h0, l0);
    pack_pair(v.z, v.w, h1, l1);
    uint32_t* hp = (uint32_t*)hi;
    uint32_t* lp = (uint32_t*)lo;
    hp[2*i] = h0; hp[2*i+1] = h1;
    lp[2*i] = l0; lp[2*i+1] = l1;
}

// ---------------- bf16x3 tensor-core GEMM (3-stage cp.async pipeline) ----------
// acc = Ah*Wh + Al*Wh + Ah*Wl. mode bits: 1=GELU, 2=write fp32 C, 4=write bf16 Ch/Cl
#define APAD 24   // 16 + 8 bf16 pad
#define WPAD 136  // 128 + 8 pad
#define NSTG 3

__global__ __launch_bounds__(256)
void gemm_bf16x3_kernel(const bf16* __restrict__ Ah, const bf16* __restrict__ Al,
                        const bf16* __restrict__ Wh, const bf16* __restrict__ Wl,
                        const float* __restrict__ bias, float* __restrict__ C,
                        bf16* __restrict__ Ch, bf16* __restrict__ Cl,
                        int M, int N, int K, int mode)
{
    __shared__ __align__(16) bf16 sAh[NSTG][128][APAD];
    __shared__ __align__(16) bf16 sAl[NSTG][128][APAD];
    __shared__ __align__(16) bf16 sWh[NSTG][16][WPAD];
    __shared__ __align__(16) bf16 sWl[NSTG][16][WPAD];

    const int tid = threadIdx.x;
    const int row0 = blockIdx.y * 128, col0 = blockIdx.x * 128;

    const char* pAh = (const char*)(Ah + (size_t)(row0 + (tid>>1)) * K + (tid&1)*8);
    const char* pAl = (const char*)(Al + (size_t)(row0 + (tid>>1)) * K + (tid&1)*8);
    const char* pWh = (const char*)(Wh + (size_t)(tid>>4) * N + col0 + (tid&15)*8);
    const char* pWl = (const char*)(Wl + (size_t)(tid>>4) * N + col0 + (tid&15)*8);

    const uint32_t aAh = (uint32_t)__cvta_generic_to_shared(&sAh[0][0][0]);
    const uint32_t aAl = (uint32_t)__cvta_generic_to_shared(&sAl[0][0][0]);
    const uint32_t aWh = (uint32_t)__cvta_generic_to_shared(&sWh[0][0][0]);
    const uint32_t aWl = (uint32_t)__cvta_generic_to_shared(&sWl[0][0][0]);
    const uint32_t SA = 128*APAD*2, SW = 16*WPAD*2;
    const uint32_t dA = ((tid>>1)*APAD + (tid&1)*8) * 2;
    const uint32_t dW = ((tid>>4)*WPAD + (tid&15)*8) * 2;

    float acc[4][4][4];
    #pragma unroll
    for (int i = 0; i < 4; i++)
        #pragma unroll
        for (int j = 0; j < 4; j++)
            #pragma unroll
            for (int t = 0; t < 4; t++) acc[i][j][t] = 0.0f;

    const int wid = tid >> 5, lane = tid & 31;
    const int wm = wid & 1;
    const int wn = wid >> 1;
    const int lrow = lane & 15, lk = (lane >> 4) * 8;
    const uint32_t offA0 = (uint32_t)(((wm*64 + lrow) * APAD + lk) * 2);
    const uint32_t offB0 = (uint32_t)(((lane & 15) * WPAD + wn*32 + (lane>>4)*8) * 2);

    const int nit = K / 16;

    // stage loader: 1 cp16 per thread per buffer
    auto load_stage = [&](int st, int it2) {
        size_t ka = (size_t)it2 * 16 * 2;
        size_t kw = (size_t)it2 * 16 * (size_t)N * 2;
        cp16(aAh + (uint32_t)st*SA + dA, pAh + ka);
        cp16(aAl + (uint32_t)st*SA + dA, pAl + ka);
        cp16(aWh + (uint32_t)st*SW + dW, pWh + kw);
        cp16(aWl + (uint32_t)st*SW + dW, pWl + kw);
        cp_commit();
    };

    // prologue: stages 0 and 1
    load_stage(0, 0);
    load_stage(1, 1);

    for (int it = 0; it < nit; ++it) {
        if (it == nit - 1) cp_wait0(); else cp_wait1();
        __syncthreads();
        if (it + 2 < nit)
            load_stage((it + 2) % NSTG, it + 2);
        const uint32_t s = (uint32_t)(it % NSTG);

        uint32_t afh[4][4], afl[4][4];
        #pragma unroll
        for (int mi = 0; mi < 4; mi++)
            ldsm4(afh[mi], aAh + s*SA + offA0 + mi*16*APAD*2);
        #pragma unroll
        for (int mi = 0; mi < 4; mi++)
            ldsm4(afl[mi], aAl + s*SA + offA0 + mi*16*APAD*2);

        uint32_t bfr[4][2];
        #pragma unroll
        for (int ng = 0; ng < 2; ng++)
            ldsm4t(bfr[2*ng][0], bfr[2*ng][1], bfr[2*ng+1][0], bfr[2*ng+1][1],
                   aWh + s*SW + offB0 + (uint32_t)(ng*16*2));
        #pragma unroll
        for (int mi = 0; mi < 4; mi++)
            #pragma unroll
            for (int ni = 0; ni < 4; ni++) {
                mma16816(acc[mi][ni], afh[mi], bfr[ni][0], bfr[ni][1]);
                mma16816(acc[mi][ni], afl[mi], bfr[ni][0], bfr[ni][1]);
            }
        #pragma unroll
        for (int ng = 0; ng < 2; ng++)
            ldsm4t(bfr[2*ng][0], bfr[2*ng][1], bfr[2*ng+1][0], bfr[2*ng+1][1],
                   aWl + s*SW + offB0 + (uint32_t)(ng*16*2));
        #pragma unroll
        for (int mi = 0; mi < 4; mi++)
            #pragma unroll
            for (int ni = 0; ni < 4; ni++)
                mma16816(acc[mi][ni], afh[mi], bfr[ni][0], bfr[ni][1]);
    }

    // epilogue
    #pragma unroll
    for (int mi = 0; mi < 4; mi++) {
        #pragma unroll
        for (int ni = 0; ni < 4; ni++) {
            int c = col0 + wn*32 + ni*8 + (lane & 3)*2;
            float bx = bias[c], by = bias[c + 1];
            #pragma unroll
            for (int rh = 0; rh < 2; rh++) {
                size_t r = (size_t)(row0 + wm*64 + mi*16 + (lane >> 2) + rh*8);
                float v0 = acc[mi][ni][2*rh]     + bx;
                float v1 = acc[mi][ni][2*rh + 1] + by;
                if (mode & 1) {
                    v0 = 0.5f * v0 * (1.0f + erff(v0 * 0.70710678118654752f));
                    v1 = 0.5f * v1 * (1.0f + erff(v1 * 0.70710678118654752f));
                }
                if (mode & 2) {
                    float2 o; o.x = v0; o.y = v1;
                    *(float2*)&C[r * N + c] = o;
                }
                if (mode & 4) {
                    uint32_t hp, lp;
                    pack_pair(v0, v1, hp, lp);
                    *(uint32_t*)&Ch[r * N + c] = hp;
                    *(uint32_t*)&Cl[r * N + c] = lp;
                }
            }
        }
    }
}

// ---------------- sigmoid gate ----------------------
__global__ __launch_bounds__(256)
void gate_kernel(const float* __restrict__ x, const float* __restrict__ wg,
                 const float* __restrict__ bg, float* __restrict__ gate)
{
    __shared__ float wgs[Dsz][8];
    int hg = blockIdx.y;
    int tid = threadIdx.x;
    for (int idx = tid; idx < Dsz*8; idx += 256)
        wgs[idx >> 3][idx & 7] = wg[(idx >> 3) * Hsz + hg*8 + (idx & 7)];
    __syncthreads();

    int h = tid & 7, r = tid >> 3;
    int m = blockIdx.x * 32 + r;
    const float4* xr = (const float4*)(x + (size_t)m * Dsz);
    float s = 0.0f;
    #pragma unroll 4
    for (int d4 = 0; d4 < Dsz/4; d4++) {
        float4 xv = xr[d4];
        s = fmaf(xv.x, wgs[d4*4 + 0][h], s);
        s = fmaf(xv.y, wgs[d4*4 + 1][h], s);
        s = fmaf(xv.z, wgs[d4*4 + 2][h], s);
        s = fmaf(xv.w, wgs[d4*4 + 3][h], s);
    }
    s += bg[hg*8 + h];
    gate[(size_t)m * Hsz + hg*8 + h] = 1.0f / (1.0f + __expf(-s));
}

// ---------------- tensor-core flash attention ----------------
#define FPAD 72
#define KV_STRIDE (64*FPAD)
#define STAGE_ELEMS (4*KV_STRIDE)
#define FLASH_SMEM (2*STAGE_ELEMS*2 + 2*64*4)

__global__ __launch_bounds__(128, 3)
void flash_tc_kernel(const bf16* __restrict__ Qh, const bf16* __restrict__ Ql,
                     const bf16* __restrict__ Kh, const bf16* __restrict__ Kl,
                     const bf16* __restrict__ Vh, const bf16* __restrict__ Vl,
                     const float* __restrict__ gate, const int* __restrict__ mask,
                     bf16* __restrict__ Ch, bf16* __restrict__ Cl)
{
    extern __shared__ __align__(16) char dynsmem[];
    int* smsk = (int*)(dynsmem + (size_t)2*STAGE_ELEMS*2);

    const int tid = threadIdx.x, lane = tid & 31, warp = tid >> 5;
    const int qt = blockIdx.x, h = blockIdx.y, b = blockIdx.z;
    const size_t rowbase = (size_t)b * Ssz;
    const size_t hoff = (size_t)h * DKsz;

    const uint32_t sbase = (uint32_t)__cvta_generic_to_shared(dynsmem);
    const uint32_t mbase = (uint32_t)__cvta_generic_to_shared(smsk);

    {
        int r = tid >> 1;
        size_t gq = (rowbase + qt*64 + r) * Dsz + hoff;
        #pragma unroll
        for (int j = 0; j < 4; j++) {
            int c8 = (tid & 1)*4 + j;
            uint32_t dof = (uint32_t)((r*FPAD + c8*8)*2);
            cp16(sbase + 0*KV_STRIDE*2 + dof, Qh + gq + c8*8);
            cp16(sbase + 1*KV_STRIDE*2 + dof, Ql + gq + c8*8);
        }
        cp_commit(); cp_wait0();
    }
    __syncthreads();

    uint32_t qfh[4][4], qfl[4][4];
    {
        uint32_t arow = (uint32_t)((warp*16 + (lane&15))*FPAD*2);
        #pragma unroll
        for (int ks = 0; ks < 4; ks++) {
            uint32_t acol = (uint32_t)((16*ks + (lane>>4)*8)*2);
            ldsm4(qfh[ks], sbase + 0*KV_STRIDE*2 + arow + acol);
            ldsm4(qfl[ks], sbase + 1*KV_STRIDE*2 + arow + acol);
        }
    }
    __syncthreads();

    float oacc[8][4];
    #pragma unroll
    for (int i = 0; i < 8; i++)
        #pragma unroll
        for (int j = 0; j < 4; j++) oacc[i][j] = 0.0f;
    float m0 = -1e30f, m1 = -1e30f, l0 = 0.0f, l1 = 0.0f;

    const int r_ld = tid >> 1;
    const int cbase = (tid & 1)*4;

    {
        size_t g = (rowbase + r_ld) * Dsz + hoff;
        #pragma unroll
        for (int j = 0; j < 4; j++) {
            int c8 = cbase + j;
            uint32_t dof = (uint32_t)((r_ld*FPAD + c8*8)*2);
            cp16(sbase + 0*KV_STRIDE*2 + dof, Kh + g + c8*8);
            cp16(sbase + 1*KV_STRIDE*2 + dof, Kl + g + c8*8);
            cp16(sbase + 2*KV_STRIDE*2 + dof, Vh + g + c8*8);
            cp16(sbase + 3*KV_STRIDE*2 + dof, Vl + g + c8*8);
        }
        if (tid < 16) cp16(mbase + tid*16, mask + rowbase + tid*4);
        cp_commit();
    }

    const int col0 = 2*(lane & 3);

    for (int kt = 0; kt < Ssz/64; kt++) {
        cp_wait0();
        __syncthreads();
        if (kt + 1 < Ssz/64) {
            int st = (kt + 1) & 1;
            size_t g = (rowbase + (kt+1)*64 + r_ld) * Dsz + hoff;
            uint32_t sb = sbase + (uint32_t)(st*STAGE_ELEMS*2);
            #pragma unroll
            for (int j = 0; j < 4; j++) {
                int c8 = cbase + j;
                uint32_t dof = (uint32_t)((r_ld*FPAD + c8*8)*2);
                cp16(sb + 0*KV_STRIDE*2 + dof, Kh + g + c8*8);
                cp16(sb + 1*KV_STRIDE*2 + dof, Kl + g + c8*8);
                cp16(sb + 2*KV_STRIDE*2 + dof, Vh + g + c8*8);
                cp16(sb + 3*KV_STRIDE*2 + dof, Vl + g + c8*8);
            }
            if (tid < 16) cp16(mbase + st*256 + tid*16, mask + rowbase + (kt+1)*64 + tid*4);
            cp_commit();
        }
        const int st = kt & 1;
        const uint32_t kb = sbase + (uint32_t)(st*STAGE_ELEMS*2);

        float sc[8][4];
        #pragma unroll
        for (int i = 0; i < 8; i++)
            #pragma unroll
            for (int j = 0; j < 4; j++) sc[i][j] = 0.0f;

        const uint32_t brow = (uint32_t)(((lane&7) + ((lane>>1)&8)) * FPAD * 2);
        const uint32_t bcol = (uint32_t)((lane & 8) * 2);
        #pragma unroll
        for (int ng = 0; ng < 4; ng++) {
            #pragma unroll
            for (int ks = 0; ks < 4; ks++) {
                uint32_t ba = kb + brow + (uint32_t)(16*ng*FPAD*2) + bcol + (uint32_t)(16*ks*2);
                uint32_t bh4[4], bl4[4];
                ldsm4(bh4, ba);
                ldsm4(bl4, ba + KV_STRIDE*2);
                mma16816(sc[2*ng],   qfh[ks], bh4[0], bh4[1]);
                mma16816(sc[2*ng+1], qfh[ks], bh4[2], bh4[3]);
                mma16816(sc[2*ng],   qfl[ks], bh4[0], bh4[1]);
                mma16816(sc[2*ng+1], qfl[ks], bh4[2], bh4[3]);
                mma16816(sc[2*ng],   qfh[ks], bl4[0], bl4[1]);
                mma16816(sc[2*ng+1], qfh[ks], bl4[2], bl4[3]);
            }
        }

        const int* mk = smsk + st*64;
        float mx0 = -1e30f, mx1 = -1e30f;
        #pragma unroll
        for (int ni = 0; ni < 8; ni++) {
            int c = 8*ni + col0;
            bool z0 = (mk[c] == 0), z1 = (mk[c+1] == 0);
            sc[ni][0] = z0 ? -1e9f : sc[ni][0]*0.125f;
            sc[ni][1] = z1 ? -1e9f : sc[ni][1]*0.125f;
            sc[ni][2] = z0 ? -1e9f : sc[ni][2]*0.125f;
            sc[ni][3] = z1 ? -1e9f : sc[ni][3]*0.125f;
            mx0 = fmaxf(mx0, fmaxf(sc[ni][0], sc[ni][1]));
            mx1 = fmaxf(mx1, fmaxf(sc[ni][2], sc[ni][3]));
        }
        mx0 = fmaxf(mx0, __shfl_xor_sync(0xffffffffu, mx0, 1));
        mx0 = fmaxf(mx0, __shfl_xor_sync(0xffffffffu, mx0, 2));
        mx1 = fmaxf(mx1, __shfl_xor_sync(0xffffffffu, mx1, 1));
        mx1 = fmaxf(mx1, __shfl_xor_sync(0xffffffffu, mx1, 2));
        float mn0 = fmaxf(m0, mx0), mn1 = fmaxf(m1, mx1);
        float al0 = __expf(m0 - mn0), al1 = __expf(m1 - mn1);
        float rs0 = 0.0f, rs1 = 0.0f;
        #pragma unroll
        for (int ni = 0; ni < 8; ni++) {
            sc[ni][0] = __expf(sc[ni][0] - mn0);
            sc[ni][1] = __expf(sc[ni][1] - mn0);
            sc[ni][2] = __expf(sc[ni][2] - mn1);
            sc[ni][3] = __expf(sc[ni][3] - mn1);
            rs0 += sc[ni][0] + sc[ni][1];
            rs1 += sc[ni][2] + sc[ni][3];
        }
        rs0 += __shfl_xor_sync(0xffffffffu, rs0, 1);
        rs0 += __shfl_xor_sync(0xffffffffu, rs0, 2);
        rs1 += __shfl_xor_sync(0xffffffffu, rs1, 1);
        rs1 += __shfl_xor_sync(0xffffffffu, rs1, 2);
        l0 = l0*al0 + rs0; l1 = l1*al1 + rs1;
        m0 = mn0; m1 = mn1;
        #pragma unroll
        for (int ni = 0; ni < 8; ni++) {
            oacc[ni][0] *= al0; oacc[ni][1] *= al0;
            oacc[ni][2] *= al1; oacc[ni][3] *= al1;
        }

        const uint32_t vrow0 = (uint32_t)((lane&15)*FPAD*2);
        const uint32_t vcol0 = (uint32_t)(((lane>>4)*8)*2);
        #pragma unroll
        for (int ki = 0; ki < 4; ki++) {
            uint32_t ph[4], pl[4];
            pack_pair(sc[2*ki][0],   sc[2*ki][1],   ph[0], pl[0]);
            pack_pair(sc[2*ki][2],   sc[2*ki][3],   ph[1], pl[1]);
            pack_pair(sc[2*ki+1][0], sc[2*ki+1][1], ph[2], pl[2]);
            pack_pair(sc[2*ki+1][2], sc[2*ki+1][3], ph[3], pl[3]);
            uint32_t va0 = kb + 2*KV_STRIDE*2 + vrow0 + (uint32_t)(16*ki*FPAD*2) + vcol0;
            #pragma unroll
            for (int ngd = 0; ngd < 4; ngd++) {
                uint32_t vh4[4], vl4[4];
                ldsm4t(vh4[0], vh4[1], vh4[2], vh4[3], va0 + (uint32_t)(16*ngd*2));
                ldsm4t(vl4[0], vl4[1], vl4[2], vl4[3], va0 + KV_STRIDE*2 + (uint32_t)(16*ngd*2));
                mma16816(oacc[2*ngd],   ph, vh4[0], vh4[1]);
                mma16816(oacc[2*ngd+1], ph, vh4[2], vh4[3]);
                mma16816(oacc[2*ngd],   ph, vl4[0], vl4[1]);
                mma16816(oacc[2*ngd+1], ph, vl4[2], vl4[3]);
                mma16816(oacc[2*ngd],   pl, vh4[0], vh4[1]);
                mma16816(oacc[2*ngd+1], pl, vh4[2], vh4[3]);
            }
        }
    }

    int q0 = qt*64 + warp*16 + (lane >> 2);
    float f0 = gate[(rowbase + q0)*Hsz + h] / l0;
    float f1 = gate[(rowbase + q0 + 8)*Hsz + h] / l1;
    #pragma unroll
    for (int ni = 0; ni < 8; ni++) {
        size_t o0 = (rowbase + q0) * Dsz + hoff + 8*ni + col0;
        size_t o1 = o0 + (size_t)8 * Dsz;
        uint32_t hp, lp;
        pack_pair(oacc[ni][0]*f0, oacc[ni][1]*f0, hp, lp);
        *(uint32_t*)&Ch[o0] = hp;
        *(uint32_t*)&Cl[o0] = lp;
        pack_pair(oacc[ni][2]*f1, oacc[ni][3]*f1, hp, lp);
        *(uint32_t*)&Ch[o1] = hp;
        *(uint32_t*)&Cl[o1] = lp;
    }
}

// ---------------- fused residual add + LayerNorm (+ optional bf16 split out) ----
__global__ __launch_bounds__(256)
void add_ln_kernel(const float* __restrict__ a, const float* __restrict__ bsrc,
                   const float* __restrict__ g, const float* __restrict__ beta,
                   float* __restrict__ out, bf16* __restrict__ oh, bf16* __restrict__ ol)
{
    int row = blockIdx.x;
    int tid = threadIdx.x;
    __shared__ float buf[Dsz];
    __shared__ float rsum[8], rsq[8];

    size_t base = (size_t)row * Dsz;
    float ls = 0.0f, lq = 0.0f;
    for (int d = tid; d < Dsz; d += 256) {
        float v = a[base + d] + bsrc[base + d];
        buf[d] = v;
        ls += v; lq += v * v;
    }
    int warp = tid >> 5, lane = tid & 31;
    for (int off = 16; off; off >>= 1) {
        ls += __shfl_xor_sync(0xffffffffu, ls, off);
        lq += __shfl_xor_sync(0xffffffffu, lq, off);
    }
    if (lane == 0) { rsum[warp] = ls; rsq[warp] = lq; }
    __syncthreads();
    float ts = 0.0f, tq = 0.0f;
    #pragma unroll
    for (int w = 0; w < 8; w++) { ts += rsum[w]; tq += rsq[w]; }
    float mean = ts * (1.0f / Dsz);
    float var  = tq * (1.0f / Dsz) - mean * mean;
    float rstd = rsqrtf(var + 1e-5f);
    for (int d = tid; d < Dsz; d += 256) {
        float v = (buf[d] - mean) * rstd * g[d] + beta[d];
        out[base + d] = v;
        if (oh) {
            bf16 hv = __float2bfloat16(v);
            oh[base + d] = hv;
            ol[base + d] = __float2bfloat16(v - __bfloat162float(hv));
        }
    }
}

// ---------------- launch ----------------
static inline void split_launch(const float* src, bf16* h, bf16* l, size_t n)
{
    int n4 = (int)(n / 4);
    split_kernel<<<(n4 + 255) / 256, 256>>>(src, h, l, n4);
}

extern "C" void kernel_launch(void* const* d_in, const int* in_sizes, int n_in,
                              void* d_out, int out_size)
{
    const float* x     = (const float*)d_in[0];
    const float* w_q   = (const float*)d_in[1];
    const float* b_q   = (const float*)d_in[2];
    const float* w_k   = (const float*)d_in[3];
    const float* b_k   = (const float*)d_in[4];
    const float* w_v   = (const float*)d_in[5];
    const float* b_v   = (const float*)d_in[6];
    const float* w_o   = (const float*)d_in[7];
    const float* b_o   = (const float*)d_in[8];
    const float* w_g   = (const float*)d_in[9];
    const float* b_g   = (const float*)d_in[10];
    const float* w1    = (const float*)d_in[11];
    const float* b1    = (const float*)d_in[12];
    const float* w2    = (const float*)d_in[13];
    const float* b2    = (const float*)d_in[14];
    const float* g1    = (const float*)d_in[15];
    const float* beta1 = (const float*)d_in[16];
    const float* g2    = (const float*)d_in[17];
    const float* beta2 = (const float*)d_in[18];
    const int*   mask  = (const int*)  d_in[19];
    float* out = (float*)d_out;

    float *tmp, *x1, *gate;
    cudaGetSymbolAddress((void**)&tmp,  g_tmp);
    cudaGetSymbolAddress((void**)&x1,   g_x1);
    cudaGetSymbolAddress((void**)&gate, g_gate);

    bf16 *xh,*xl,*qh,*ql,*kh,*kl,*vh,*vl,*ctxh,*ctxl,*x1h,*x1l,*ffh,*ffl;
    bf16 *wqh,*wql,*wkh,*wkl,*wvh,*wvl,*woh,*wol,*w1h,*w1l,*w2h,*w2l;
    cudaGetSymbolAddress((void**)&xh,  g_xh);   cudaGetSymbolAddress((void**)&xl,  g_xl);
    cudaGetSymbolAddress((void**)&qh,  g_qh);   cudaGetSymbolAddress((void**)&ql,  g_ql);
    cudaGetSymbolAddress((void**)&kh,  g_kh);   cudaGetSymbolAddress((void**)&kl,  g_kl);
    cudaGetSymbolAddress((void**)&vh,  g_vh);   cudaGetSymbolAddress((void**)&vl,  g_vl);
    cudaGetSymbolAddress((void**)&ctxh,g_ctxh); cudaGetSymbolAddress((void**)&ctxl,g_ctxl);
    cudaGetSymbolAddress((void**)&x1h, g_x1h);  cudaGetSymbolAddress((void**)&x1l, g_x1l);
    cudaGetSymbolAddress((void**)&ffh, g_ffh);  cudaGetSymbolAddress((void**)&ffl, g_ffl);
    cudaGetSymbolAddress((void**)&wqh, g_wqh);  cudaGetSymbolAddress((void**)&wql, g_wql);
    cudaGetSymbolAddress((void**)&wkh, g_wkh);  cudaGetSymbolAddress((void**)&wkl, g_wkl);
    cudaGetSymbolAddress((void**)&wvh, g_wvh);  cudaGetSymbolAddress((void**)&wvl, g_wvl);
    cudaGetSymbolAddress((void**)&woh, g_woh);  cudaGetSymbolAddress((void**)&wol, g_wol);
    cudaGetSymbolAddress((void**)&w1h, g_w1h);  cudaGetSymbolAddress((void**)&w1l, g_w1l);
    cudaGetSymbolAddress((void**)&w2h, g_w2h);  cudaGetSymbolAddress((void**)&w2l, g_w2l);

    cudaFuncSetAttribute(flash_tc_kernel,
                         cudaFuncAttributeMaxDynamicSharedMemorySize, FLASH_SMEM);

    dim3 gSq(Dsz/128, Msz/128);      // (8, 64)
    dim3 gF1(DFFsz/128, Msz/128);    // (32, 64)

    // Launch order arranged so ncu (-s 5 -c 1) profiles the Q-projection GEMM.
    split_launch(x,   xh,  xl,  (size_t)Msz*Dsz);    // 0
    split_launch(w_q, wqh, wql, (size_t)Dsz*Dsz);    // 1
    split_launch(w_k, wkh, wkl, (size_t)Dsz*Dsz);    // 2
    split_launch(w_v, wvh, wvl, (size_t)Dsz*Dsz);    // 3
    split_launch(w_o, woh, wol, (size_t)Dsz*Dsz);    // 4

    gemm_bf16x3_kernel<<<gSq, 256>>>(xh, xl, wqh, wql, b_q, nullptr, qh, ql, Msz, Dsz, Dsz, 4);  // 5 <- profiled
    gemm_bf16x3_kernel<<<gSq, 256>>>(xh, xl, wkh, wkl, b_k, nullptr, kh, kl, Msz, Dsz, Dsz, 4);  // 6
    gemm_bf16x3_kernel<<<gSq, 256>>>(xh, xl, wvh, wvl, b_v, nullptr, vh, vl, Msz, Dsz, Dsz, 4);  // 7

    split_launch(w1,  w1h, w1l, (size_t)Dsz*DFFsz);  // 8
    split_launch(w2,  w2h, w2l, (size_t)DFFsz*Dsz);  // 9
    gate_kernel<<<dim3(Msz/32, 2), 256>>>(x, w_g, b_g, gate);   // 10

    flash_tc_kernel<<<dim3(Ssz/64, Hsz, Bsz), 128, FLASH_SMEM>>>(
        qh, ql, kh, kl, vh, vl, gate, mask, ctxh, ctxl);        // 11

    gemm_bf16x3_kernel<<<gSq, 256>>>(ctxh, ctxl, woh, wol, b_o, tmp, nullptr, nullptr, Msz, Dsz, Dsz, 2);
    add_ln_kernel<<<Msz, 256>>>(x, tmp, g1, beta1, x1, x1h, x1l);

    gemm_bf16x3_kernel<<<gF1, 256>>>(x1h, x1l, w1h, w1l, b1, nullptr, ffh, ffl, Msz, DFFsz, Dsz, 5);
    gemm_bf16x3_kernel<<<gSq, 256>>>(ffh, ffl, w2h, w2l, b2, tmp, nullptr, nullptr, Msz, Dsz, DFFsz, 2);
    add_ln_kernel<<<Msz, 256>>>(x1, tmp, g2, beta2, out, nullptr, nullptr);
}

// round 7
// speedup vs baseline: 2.3656x; 1.0513x over previous
#include <cuda_runtime.h>
#include <cuda_bf16.h>
#include <math.h>
#include <cstdint>

// Problem constants
#define Bsz   4
#define Ssz   2048
#define Dsz   1024
#define Hsz   16
#define DKsz  64
#define DFFsz 4096
#define Msz   (Bsz*Ssz)   // 8192 rows

typedef __nv_bfloat16 bf16;

// ---------------- scratch (static device globals; no allocation) ----------------
__device__ float g_tmp [(size_t)Msz*Dsz];
__device__ float g_x1  [(size_t)Msz*Dsz];
__device__ float g_gate[(size_t)Msz*Hsz];

__device__ bf16 g_xh [(size_t)Msz*Dsz],   g_xl [(size_t)Msz*Dsz];
__device__ bf16 g_qh [(size_t)Msz*Dsz],   g_ql [(size_t)Msz*Dsz];
__device__ bf16 g_kh [(size_t)Msz*Dsz],   g_kl [(size_t)Msz*Dsz];
__device__ bf16 g_vh [(size_t)Msz*Dsz],   g_vl [(size_t)Msz*Dsz];
__device__ bf16 g_ctxh[(size_t)Msz*Dsz],  g_ctxl[(size_t)Msz*Dsz];
__device__ bf16 g_x1h[(size_t)Msz*Dsz],   g_x1l[(size_t)Msz*Dsz];
__device__ bf16 g_ffh[(size_t)Msz*DFFsz], g_ffl[(size_t)Msz*DFFsz];
__device__ bf16 g_wqh[(size_t)Dsz*Dsz],   g_wql[(size_t)Dsz*Dsz];
__device__ bf16 g_wkh[(size_t)Dsz*Dsz],   g_wkl[(size_t)Dsz*Dsz];
__device__ bf16 g_wvh[(size_t)Dsz*Dsz],   g_wvl[(size_t)Dsz*Dsz];
__device__ bf16 g_woh[(size_t)Dsz*Dsz],   g_wol[(size_t)Dsz*Dsz];
__device__ bf16 g_w1h[(size_t)Dsz*DFFsz], g_w1l[(size_t)Dsz*DFFsz];
__device__ bf16 g_w2h[(size_t)DFFsz*Dsz], g_w2l[(size_t)DFFsz*Dsz];

// ---------------- small helpers ----------------
__device__ __forceinline__ void cp16(uint32_t dst, const void* src) {
    asm volatile("cp.async.ca.shared.global [%0], [%1], 16;\n" :: "r"(dst), "l"(src));
}
__device__ __forceinline__ void cp_commit() {
    asm volatile("cp.async.commit_group;\n");
}
__device__ __forceinline__ void cp_wait0() {
    asm volatile("cp.async.wait_group 0;\n");
}
__device__ __forceinline__ void cp_wait1() {
    asm volatile("cp.async.wait_group 1;\n");
}
__device__ __forceinline__ void ldsm4(uint32_t* r, uint32_t addr) {
    asm volatile("ldmatrix.sync.aligned.m8n8.x4.shared.b16 {%0,%1,%2,%3}, [%4];"
                 : "=r"(r[0]), "=r"(r[1]), "=r"(r[2]), "=r"(r[3]) : "r"(addr));
}
__device__ __forceinline__ void ldsm4t(uint32_t& r0, uint32_t& r1,
                                       uint32_t& r2, uint32_t& r3, uint32_t addr) {
    asm volatile("ldmatrix.sync.aligned.m8n8.x4.trans.shared.b16 {%0,%1,%2,%3}, [%4];"
                 : "=r"(r0), "=r"(r1), "=r"(r2), "=r"(r3) : "r"(addr));
}
__device__ __forceinline__ void mma16816(float* ac, const uint32_t* a,
                                         uint32_t b0, uint32_t b1) {
    asm volatile(
        "mma.sync.aligned.m16n8k16.row.col.f32.bf16.bf16.f32 "
        "{%0,%1,%2,%3},{%4,%5,%6,%7},{%8,%9},{%0,%1,%2,%3};"
        : "+f"(ac[0]), "+f"(ac[1]), "+f"(ac[2]), "+f"(ac[3])
        : "r"(a[0]), "r"(a[1]), "r"(a[2]), "r"(a[3]), "r"(b0), "r"(b1));
}
__device__ __forceinline__ void pack_pair(float a, float b, uint32_t& hi, uint32_t& lo) {
    bf16 ha = __float2bfloat16(a), hb = __float2bfloat16(b);
    bf16 la = __float2bfloat16(a - __bfloat162float(ha));
    bf16 lb = __float2bfloat16(b - __bfloat162float(hb));
    __nv_bfloat162 th = __halves2bfloat162(ha, hb);
    __nv_bfloat162 tl = __halves2bfloat162(la, lb);
    hi = *(uint32_t*)&th; lo = *(uint32_t*)&tl;
}

// ---------------- fused split of x + all 6 weights (one launch) ----------------
// segments in float4 blocks of 256:
//   x:8192 | wq:1024 | wk:1024 | wv:1024 | wo:1024 | w1:4096 | w2:4096  = 20480
struct SplitArgs {
    const float* src[7];
    bf16* hi[7];
    bf16* lo[7];
};
__global__ __launch_bounds__(256)
void split_all_kernel(SplitArgs a)
{
    int bid = blockIdx.x;
    int seg, base;
    if      (bid < 8192)  { seg = 0; base = 0; }
    else if (bid < 9216)  { seg = 1; base = 8192; }
    else if (bid < 10240) { seg = 2; base = 9216; }
    else if (bid < 11264) { seg = 3; base = 10240; }
    else if (bid < 12288) { seg = 4; base = 11264; }
    else if (bid < 16384) { seg = 5; base = 12288; }
    else                  { seg = 6; base = 16384; }
    size_t i = (size_t)(bid - base) * 256 + threadIdx.x;
    float4 v = ((const float4*)a.src[seg])[i];
    uint32_t h0, l0, h1, l1;
    pack_pair(v.x, v.y, h0, l0);
    pack_pair(v.z, v.w, h1, l1);
    uint32_t* hp = (uint32_t*)a.hi[seg];
    uint32_t* lp = (uint32_t*)a.lo[seg];
    hp[2*i] = h0; hp[2*i+1] = h1;
    lp[2*i] = l0; lp[2*i+1] = l1;
}

// ---------------- bf16x3 tensor-core GEMM core (3-stage cp.async) ----------
// acc = Ah*Wh + Al*Wh + Ah*Wl. mode bits: 1=GELU, 2=write fp32 C, 4=write bf16 Ch/Cl
#define APAD 24
#define WPAD 136
#define NSTG 3

__device__ __forceinline__
void gemm_core(const bf16* __restrict__ Ah, const bf16* __restrict__ Al,
               const bf16* __restrict__ Wh, const bf16* __restrict__ Wl,
               const float* __restrict__ bias, float* __restrict__ C,
               bf16* __restrict__ Ch, bf16* __restrict__ Cl,
               int N, int K, int mode, int row0, int col0)
{
    __shared__ __align__(16) bf16 sAh[NSTG][128][APAD];
    __shared__ __align__(16) bf16 sAl[NSTG][128][APAD];
    __shared__ __align__(16) bf16 sWh[NSTG][16][WPAD];
    __shared__ __align__(16) bf16 sWl[NSTG][16][WPAD];

    const int tid = threadIdx.x;

    const char* pAh = (const char*)(Ah + (size_t)(row0 + (tid>>1)) * K + (tid&1)*8);
    const char* pAl = (const char*)(Al + (size_t)(row0 + (tid>>1)) * K + (tid&1)*8);
    const char* pWh = (const char*)(Wh + (size_t)(tid>>4) * N + col0 + (tid&15)*8);
    const char* pWl = (const char*)(Wl + (size_t)(tid>>4) * N + col0 + (tid&15)*8);

    const uint32_t aAh = (uint32_t)__cvta_generic_to_shared(&sAh[0][0][0]);
    const uint32_t aAl = (uint32_t)__cvta_generic_to_shared(&sAl[0][0][0]);
    const uint32_t aWh = (uint32_t)__cvta_generic_to_shared(&sWh[0][0][0]);
    const uint32_t aWl = (uint32_t)__cvta_generic_to_shared(&sWl[0][0][0]);
    const uint32_t SA = 128*APAD*2, SW = 16*WPAD*2;
    const uint32_t dA = ((tid>>1)*APAD + (tid&1)*8) * 2;
    const uint32_t dW = ((tid>>4)*WPAD + (tid&15)*8) * 2;

    float acc[4][4][4];
    #pragma unroll
    for (int i = 0; i < 4; i++)
        #pragma unroll
        for (int j = 0; j < 4; j++)
            #pragma unroll
            for (int t = 0; t < 4; t++) acc[i][j][t] = 0.0f;

    const int wid = tid >> 5, lane = tid & 31;
    const int wm = wid & 1;
    const int wn = wid >> 1;
    const int lrow = lane & 15, lk = (lane >> 4) * 8;
    const uint32_t offA0 = (uint32_t)(((wm*64 + lrow) * APAD + lk) * 2);
    const uint32_t offB0 = (uint32_t)(((lane & 15) * WPAD + wn*32 + (lane>>4)*8) * 2);

    const int nit = K / 16;

    auto load_stage = [&](int st, int it2) {
        size_t ka = (size_t)it2 * 16 * 2;
        size_t kw = (size_t)it2 * 16 * (size_t)N * 2;
        cp16(aAh + (uint32_t)st*SA + dA, pAh + ka);
        cp16(aAl + (uint32_t)st*SA + dA, pAl + ka);
        cp16(aWh + (uint32_t)st*SW + dW, pWh + kw);
        cp16(aWl + (uint32_t)st*SW + dW, pWl + kw);
        cp_commit();
    };

    load_stage(0, 0);
    load_stage(1, 1);

    for (int it = 0; it < nit; ++it) {
        if (it == nit - 1) cp_wait0(); else cp_wait1();
        __syncthreads();
        if (it + 2 < nit)
            load_stage((it + 2) % NSTG, it + 2);
        const uint32_t s = (uint32_t)(it % NSTG);

        uint32_t afh[4][4], afl[4][4];
        #pragma unroll
        for (int mi = 0; mi < 4; mi++)
            ldsm4(afh[mi], aAh + s*SA + offA0 + mi*16*APAD*2);
        #pragma unroll
        for (int mi = 0; mi < 4; mi++)
            ldsm4(afl[mi], aAl + s*SA + offA0 + mi*16*APAD*2);

        uint32_t bfr[4][2];
        #pragma unroll
        for (int ng = 0; ng < 2; ng++)
            ldsm4t(bfr[2*ng][0], bfr[2*ng][1], bfr[2*ng+1][0], bfr[2*ng+1][1],
                   aWh + s*SW + offB0 + (uint32_t)(ng*16*2));
        #pragma unroll
        for (int mi = 0; mi < 4; mi++)
            #pragma unroll
            for (int ni = 0; ni < 4; ni++) {
                mma16816(acc[mi][ni], afh[mi], bfr[ni][0], bfr[ni][1]);
                mma16816(acc[mi][ni], afl[mi], bfr[ni][0], bfr[ni][1]);
            }
        #pragma unroll
        for (int ng = 0; ng < 2; ng++)
            ldsm4t(bfr[2*ng][0], bfr[2*ng][1], bfr[2*ng+1][0], bfr[2*ng+1][1],
                   aWl + s*SW + offB0 + (uint32_t)(ng*16*2));
        #pragma unroll
        for (int mi = 0; mi < 4; mi++)
            #pragma unroll
            for (int ni = 0; ni < 4; ni++)
                mma16816(acc[mi][ni], afh[mi], bfr[ni][0], bfr[ni][1]);
    }

    #pragma unroll
    for (int mi = 0; mi < 4; mi++) {
        #pragma unroll
        for (int ni = 0; ni < 4; ni++) {
            int c = col0 + wn*32 + ni*8 + (lane & 3)*2;
            float bx = bias[c], by = bias[c + 1];
            #pragma unroll
            for (int rh = 0; rh < 2; rh++) {
                size_t r = (size_t)(row0 + wm*64 + mi*16 + (lane >> 2) + rh*8);
                float v0 = acc[mi][ni][2*rh]     + bx;
                float v1 = acc[mi][ni][2*rh + 1] + by;
                if (mode & 1) {
                    v0 = 0.5f * v0 * (1.0f + erff(v0 * 0.70710678118654752f));
                    v1 = 0.5f * v1 * (1.0f + erff(v1 * 0.70710678118654752f));
                }
                if (mode & 2) {
                    float2 o; o.x = v0; o.y = v1;
                    *(float2*)&C[r * N + c] = o;
                }
                if (mode & 4) {
                    uint32_t hp, lp;
                    pack_pair(v0, v1, hp, lp);
                    *(uint32_t*)&Ch[r * N + c] = hp;
                    *(uint32_t*)&Cl[r * N + c] = lp;
                }
            }
        }
    }
}

__global__ __launch_bounds__(256)
void gemm_bf16x3_kernel(const bf16* __restrict__ Ah, const bf16* __restrict__ Al,
                        const bf16* __restrict__ Wh, const bf16* __restrict__ Wl,
                        const float* __restrict__ bias, float* __restrict__ C,
                        bf16* __restrict__ Ch, bf16* __restrict__ Cl,
                        int N, int K, int mode)
{
    gemm_core(Ah, Al, Wh, Wl, bias, C, Ch, Cl, N, K, mode,
              blockIdx.y * 128, blockIdx.x * 128);
}

// merged Q/K/V projection: blockIdx.z selects weight/output set
struct QKVArgs {
    const bf16* Wh[3];
    const bf16* Wl[3];
    const float* bias[3];
    bf16* Ch[3];
    bf16* Cl[3];
};
__global__ __launch_bounds__(256)
void qkv_gemm_kernel(const bf16* __restrict__ Ah, const bf16* __restrict__ Al,
                     QKVArgs a)
{
    int z = blockIdx.z;
    gemm_core(Ah, Al, a.Wh[z], a.Wl[z], a.bias[z], nullptr, a.Ch[z], a.Cl[z],
              Dsz, Dsz, 4, blockIdx.y * 128, blockIdx.x * 128);
}

// ---------------- sigmoid gate ----------------------
__global__ __launch_bounds__(256)
void gate_kernel(const float* __restrict__ x, const float* __restrict__ wg,
                 const float* __restrict__ bg, float* __restrict__ gate)
{
    __shared__ float wgs[Dsz][8];
    int hg = blockIdx.y;
    int tid = threadIdx.x;
    for (int idx = tid; idx < Dsz*8; idx += 256)
        wgs[idx >> 3][idx & 7] = wg[(idx >> 3) * Hsz + hg*8 + (idx & 7)];
    __syncthreads();

    int h = tid & 7, r = tid >> 3;
    int m = blockIdx.x * 32 + r;
    const float4* xr = (const float4*)(x + (size_t)m * Dsz);
    float s = 0.0f;
    #pragma unroll 4
    for (int d4 = 0; d4 < Dsz/4; d4++) {
        float4 xv = xr[d4];
        s = fmaf(xv.x, wgs[d4*4 + 0][h], s);
        s = fmaf(xv.y, wgs[d4*4 + 1][h], s);
        s = fmaf(xv.z, wgs[d4*4 + 2][h], s);
        s = fmaf(xv.w, wgs[d4*4 + 3][h], s);
    }
    s += bg[hg*8 + h];
    gate[(size_t)m * Hsz + hg*8 + h] = 1.0f / (1.0f + __expf(-s));
}

// ---------------- tensor-core flash attention ----------------
#define FPAD 72
#define KV_STRIDE (64*FPAD)
#define STAGE_ELEMS (4*KV_STRIDE)
#define FLASH_SMEM (2*STAGE_ELEMS*2 + 2*64*4)

__global__ __launch_bounds__(128, 3)
void flash_tc_kernel(const bf16* __restrict__ Qh, const bf16* __restrict__ Ql,
                     const bf16* __restrict__ Kh, const bf16* __restrict__ Kl,
                     const bf16* __restrict__ Vh, const bf16* __restrict__ Vl,
                     const float* __restrict__ gate, const int* __restrict__ mask,
                     bf16* __restrict__ Ch, bf16* __restrict__ Cl)
{
    extern __shared__ __align__(16) char dynsmem[];
    int* smsk = (int*)(dynsmem + (size_t)2*STAGE_ELEMS*2);

    const int tid = threadIdx.x, lane = tid & 31, warp = tid >> 5;
    const int qt = blockIdx.x, h = blockIdx.y, b = blockIdx.z;
    const size_t rowbase = (size_t)b * Ssz;
    const size_t hoff = (size_t)h * DKsz;

    const uint32_t sbase = (uint32_t)__cvta_generic_to_shared(dynsmem);
    const uint32_t mbase = (uint32_t)__cvta_generic_to_shared(smsk);

    {
        int r = tid >> 1;
        size_t gq = (rowbase + qt*64 + r) * Dsz + hoff;
        #pragma unroll
        for (int j = 0; j < 4; j++) {
            int c8 = (tid & 1)*4 + j;
            uint32_t dof = (uint32_t)((r*FPAD + c8*8)*2);
            cp16(sbase + 0*KV_STRIDE*2 + dof, Qh + gq + c8*8);
            cp16(sbase + 1*KV_STRIDE*2 + dof, Ql + gq + c8*8);
        }
        cp_commit(); cp_wait0();
    }
    __syncthreads();

    uint32_t qfh[4][4], qfl[4][4];
    {
        uint32_t arow = (uint32_t)((warp*16 + (lane&15))*FPAD*2);
        #pragma unroll
        for (int ks = 0; ks < 4; ks++) {
            uint32_t acol = (uint32_t)((16*ks + (lane>>4)*8)*2);
            ldsm4(qfh[ks], sbase + 0*KV_STRIDE*2 + arow + acol);
            ldsm4(qfl[ks], sbase + 1*KV_STRIDE*2 + arow + acol);
        }
    }
    __syncthreads();

    float oacc[8][4];
    #pragma unroll
    for (int i = 0; i < 8; i++)
        #pragma unroll
        for (int j = 0; j < 4; j++) oacc[i][j] = 0.0f;
    float m0 = -1e30f, m1 = -1e30f, l0 = 0.0f, l1 = 0.0f;

    const int r_ld = tid >> 1;
    const int cbase = (tid & 1)*4;

    {
        size_t g = (rowbase + r_ld) * Dsz + hoff;
        #pragma unroll
        for (int j = 0; j < 4; j++) {
            int c8 = cbase + j;
            uint32_t dof = (uint32_t)((r_ld*FPAD + c8*8)*2);
            cp16(sbase + 0*KV_STRIDE*2 + dof, Kh + g + c8*8);
            cp16(sbase + 1*KV_STRIDE*2 + dof, Kl + g + c8*8);
            cp16(sbase + 2*KV_STRIDE*2 + dof, Vh + g + c8*8);
            cp16(sbase + 3*KV_STRIDE*2 + dof, Vl + g + c8*8);
        }
        if (tid < 16) cp16(mbase + tid*16, mask + rowbase + tid*4);
        cp_commit();
    }

    const int col0 = 2*(lane & 3);

    for (int kt = 0; kt < Ssz/64; kt++) {
        cp_wait0();
        __syncthreads();
        if (kt + 1 < Ssz/64) {
            int st = (kt + 1) & 1;
            size_t g = (rowbase + (kt+1)*64 + r_ld) * Dsz + hoff;
            uint32_t sb = sbase + (uint32_t)(st*STAGE_ELEMS*2);
            #pragma unroll
            for (int j = 0; j < 4; j++) {
                int c8 = cbase + j;
                uint32_t dof = (uint32_t)((r_ld*FPAD + c8*8)*2);
                cp16(sb + 0*KV_STRIDE*2 + dof, Kh + g + c8*8);
                cp16(sb + 1*KV_STRIDE*2 + dof, Kl + g + c8*8);
                cp16(sb + 2*KV_STRIDE*2 + dof, Vh + g + c8*8);
                cp16(sb + 3*KV_STRIDE*2 + dof, Vl + g + c8*8);
            }
            if (tid < 16) cp16(mbase + st*256 + tid*16, mask + rowbase + (kt+1)*64 + tid*4);
            cp_commit();
        }
        const int st = kt & 1;
        const uint32_t kb = sbase + (uint32_t)(st*STAGE_ELEMS*2);

        float sc[8][4];
        #pragma unroll
        for (int i = 0; i < 8; i++)
            #pragma unroll
            for (int j = 0; j < 4; j++) sc[i][j] = 0.0f;

        const uint32_t brow = (uint32_t)(((lane&7) + ((lane>>1)&8)) * FPAD * 2);
        const uint32_t bcol = (uint32_t)((lane & 8) * 2);
        #pragma unroll
        for (int ng = 0; ng < 4; ng++) {
            #pragma unroll
            for (int ks = 0; ks < 4; ks++) {
                uint32_t ba = kb + brow + (uint32_t)(16*ng*FPAD*2) + bcol + (uint32_t)(16*ks*2);
                uint32_t bh4[4], bl4[4];
                ldsm4(bh4, ba);
                ldsm4(bl4, ba + KV_STRIDE*2);
                mma16816(sc[2*ng],   qfh[ks], bh4[0], bh4[1]);
                mma16816(sc[2*ng+1], qfh[ks], bh4[2], bh4[3]);
                mma16816(sc[2*ng],   qfl[ks], bh4[0], bh4[1]);
                mma16816(sc[2*ng+1], qfl[ks], bh4[2], bh4[3]);
                mma16816(sc[2*ng],   qfh[ks], bl4[0], bl4[1]);
                mma16816(sc[2*ng+1], qfh[ks], bl4[2], bl4[3]);
            }
        }

        const int* mk = smsk + st*64;
        float mx0 = -1e30f, mx1 = -1e30f;
        #pragma unroll
        for (int ni = 0; ni < 8; ni++) {
            int c = 8*ni + col0;
            bool z0 = (mk[c] == 0), z1 = (mk[c+1] == 0);
            sc[ni][0] = z0 ? -1e9f : sc[ni][0]*0.125f;
            sc[ni][1] = z1 ? -1e9f : sc[ni][1]*0.125f;
            sc[ni][2] = z0 ? -1e9f : sc[ni][2]*0.125f;
            sc[ni][3] = z1 ? -1e9f : sc[ni][3]*0.125f;
            mx0 = fmaxf(mx0, fmaxf(sc[ni][0], sc[ni][1]));
            mx1 = fmaxf(mx1, fmaxf(sc[ni][2], sc[ni][3]));
        }
        mx0 = fmaxf(mx0, __shfl_xor_sync(0xffffffffu, mx0, 1));
        mx0 = fmaxf(mx0, __shfl_xor_sync(0xffffffffu, mx0, 2));
        mx1 = fmaxf(mx1, __shfl_xor_sync(0xffffffffu, mx1, 1));
        mx1 = fmaxf(mx1, __shfl_xor_sync(0xffffffffu, mx1, 2));
        float mn0 = fmaxf(m0, mx0), mn1 = fmaxf(m1, mx1);
        float al0 = __expf(m0 - mn0), al1 = __expf(m1 - mn1);
        float rs0 = 0.0f, rs1 = 0.0f;
        #pragma unroll
        for (int ni = 0; ni < 8; ni++) {
            sc[ni][0] = __expf(sc[ni][0] - mn0);
            sc[ni][1] = __expf(sc[ni][1] - mn0);
            sc[ni][2] = __expf(sc[ni][2] - mn1);
            sc[ni][3] = __expf(sc[ni][3] - mn1);
            rs0 += sc[ni][0] + sc[ni][1];
            rs1 += sc[ni][2] + sc[ni][3];
        }
        rs0 += __shfl_xor_sync(0xffffffffu, rs0, 1);
        rs0 += __shfl_xor_sync(0xffffffffu, rs0, 2);
        rs1 += __shfl_xor_sync(0xffffffffu, rs1, 1);
        rs1 += __shfl_xor_sync(0xffffffffu, rs1, 2);
        l0 = l0*al0 + rs0; l1 = l1*al1 + rs1;
        m0 = mn0; m1 = mn1;
        #pragma unroll
        for (int ni = 0; ni < 8; ni++) {
            oacc[ni][0] *= al0; oacc[ni][1] *= al0;
            oacc[ni][2] *= al1; oacc[ni][3] *= al1;
        }

        const uint32_t vrow0 = (uint32_t)((lane&15)*FPAD*2);
        const uint32_t vcol0 = (uint32_t)(((lane>>4)*8)*2);
        #pragma unroll
        for (int ki = 0; ki < 4; ki++) {
            uint32_t ph[4], pl[4];
            pack_pair(sc[2*ki][0],   sc[2*ki][1],   ph[0], pl[0]);
            pack_pair(sc[2*ki][2],   sc[2*ki][3],   ph[1], pl[1]);
            pack_pair(sc[2*ki+1][0], sc[2*ki+1][1], ph[2], pl[2]);
            pack_pair(sc[2*ki+1][2], sc[2*ki+1][3], ph[3], pl[3]);
            uint32_t va0 = kb + 2*KV_STRIDE*2 + vrow0 + (uint32_t)(16*ki*FPAD*2) + vcol0;
            #pragma unroll
            for (int ngd = 0; ngd < 4; ngd++) {
                uint32_t vh4[4], vl4[4];
                ldsm4t(vh4[0], vh4[1], vh4[2], vh4[3], va0 + (uint32_t)(16*ngd*2));
                ldsm4t(vl4[0], vl4[1], vl4[2], vl4[3], va0 + KV_STRIDE*2 + (uint32_t)(16*ngd*2));
                mma16816(oacc[2*ngd],   ph, vh4[0], vh4[1]);
                mma16816(oacc[2*ngd+1], ph, vh4[2], vh4[3]);
                mma16816(oacc[2*ngd],   ph, vl4[0], vl4[1]);
                mma16816(oacc[2*ngd+1], ph, vl4[2], vl4[3]);
                mma16816(oacc[2*ngd],   pl, vh4[0], vh4[1]);
                mma16816(oacc[2*ngd+1], pl, vh4[2], vh4[3]);
            }
        }
    }

    int q0 = qt*64 + warp*16 + (lane >> 2);
    float f0 = gate[(rowbase + q0)*Hsz + h] / l0;
    float f1 = gate[(rowbase + q0 + 8)*Hsz + h] / l1;
    #pragma unroll
    for (int ni = 0; ni < 8; ni++) {
        size_t o0 = (rowbase + q0) * Dsz + hoff + 8*ni + col0;
        size_t o1 = o0 + (size_t)8 * Dsz;
        uint32_t hp, lp;
        pack_pair(oacc[ni][0]*f0, oacc[ni][1]*f0, hp, lp);
        *(uint32_t*)&Ch[o0] = hp;
        *(uint32_t*)&Cl[o0] = lp;
        pack_pair(oacc[ni][2]*f1, oacc[ni][3]*f1, hp, lp);
        *(uint32_t*)&Ch[o1] = hp;
        *(uint32_t*)&Cl[o1] = lp;
    }
}

// ---------------- fused residual add + LayerNorm (+ optional bf16 split out) ----
__global__ __launch_bounds__(256)
void add_ln_kernel(const float* __restrict__ a, const float* __restrict__ bsrc,
                   const float* __restrict__ g, const float* __restrict__ beta,
                   float* __restrict__ out, bf16* __restrict__ oh, bf16* __restrict__ ol)
{
    int row = blockIdx.x;
    int tid = threadIdx.x;
    __shared__ float buf[Dsz];
    __shared__ float rsum[8], rsq[8];

    size_t base = (size_t)row * Dsz;
    float ls = 0.0f, lq = 0.0f;
    for (int d = tid; d < Dsz; d += 256) {
        float v = a[base + d] + bsrc[base + d];
        buf[d] = v;
        ls += v; lq += v * v;
    }
    int warp = tid >> 5, lane = tid & 31;
    for (int off = 16; off; off >>= 1) {
        ls += __shfl_xor_sync(0xffffffffu, ls, off);
        lq += __shfl_xor_sync(0xffffffffu, lq, off);
    }
    if (lane == 0) { rsum[warp] = ls; rsq[warp] = lq; }
    __syncthreads();
    float ts = 0.0f, tq = 0.0f;
    #pragma unroll
    for (int w = 0; w < 8; w++) { ts += rsum[w]; tq += rsq[w]; }
    float mean = ts * (1.0f / Dsz);
    float var  = tq * (1.0f / Dsz) - mean * mean;
    float rstd = rsqrtf(var + 1e-5f);
    for (int d = tid; d < Dsz; d += 256) {
        float v = (buf[d] - mean) * rstd * g[d] + beta[d];
        out[base + d] = v;
        if (oh) {
            bf16 hv = __float2bfloat16(v);
            oh[base + d] = hv;
            ol[base + d] = __float2bfloat16(v - __bfloat162float(hv));
        }
    }
}

// ---------------- launch ----------------
extern "C" void kernel_launch(void* const* d_in, const int* in_sizes, int n_in,
                              void* d_out, int out_size)
{
    const float* x     = (const float*)d_in[0];
    const float* w_q   = (const float*)d_in[1];
    const float* b_q   = (const float*)d_in[2];
    const float* w_k   = (const float*)d_in[3];
    const float* b_k   = (const float*)d_in[4];
    const float* w_v   = (const float*)d_in[5];
    const float* b_v   = (const float*)d_in[6];
    const float* w_o   = (const float*)d_in[7];
    const float* b_o   = (const float*)d_in[8];
    const float* w_g   = (const float*)d_in[9];
    const float* b_g   = (const float*)d_in[10];
    const float* w1    = (const float*)d_in[11];
    const float* b1    = (const float*)d_in[12];
    const float* w2    = (const float*)d_in[13];
    const float* b2    = (const float*)d_in[14];
    const float* g1    = (const float*)d_in[15];
    const float* beta1 = (const float*)d_in[16];
    const float* g2    = (const float*)d_in[17];
    const float* beta2 = (const float*)d_in[18];
    const int*   mask  = (const int*)  d_in[19];
    float* out = (float*)d_out;

    float *tmp, *x1, *gate;
    cudaGetSymbolAddress((void**)&tmp,  g_tmp);
    cudaGetSymbolAddress((void**)&x1,   g_x1);
    cudaGetSymbolAddress((void**)&gate, g_gate);

    bf16 *xh,*xl,*qh,*ql,*kh,*kl,*vh,*vl,*ctxh,*ctxl,*x1h,*x1l,*ffh,*ffl;
    bf16 *wqh,*wql,*wkh,*wkl,*wvh,*wvl,*woh,*wol,*w1h,*w1l,*w2h,*w2l;
    cudaGetSymbolAddress((void**)&xh,  g_xh);   cudaGetSymbolAddress((void**)&xl,  g_xl);
    cudaGetSymbolAddress((void**)&qh,  g_qh);   cudaGetSymbolAddress((void**)&ql,  g_ql);
    cudaGetSymbolAddress((void**)&kh,  g_kh);   cudaGetSymbolAddress((void**)&kl,  g_kl);
    cudaGetSymbolAddress((void**)&vh,  g_vh);   cudaGetSymbolAddress((void**)&vl,  g_vl);
    cudaGetSymbolAddress((void**)&ctxh,g_ctxh); cudaGetSymbolAddress((void**)&ctxl,g_ctxl);
    cudaGetSymbolAddress((void**)&x1h, g_x1h);  cudaGetSymbolAddress((void**)&x1l, g_x1l);
    cudaGetSymbolAddress((void**)&ffh, g_ffh);  cudaGetSymbolAddress((void**)&ffl, g_ffl);
    cudaGetSymbolAddress((void**)&wqh, g_wqh);  cudaGetSymbolAddress((void**)&wql, g_wql);
    cudaGetSymbolAddress((void**)&wkh, g_wkh);  cudaGetSymbolAddress((void**)&wkl, g_wkl);
    cudaGetSymbolAddress((void**)&wvh, g_wvh);  cudaGetSymbolAddress((void**)&wvl, g_wvl);
    cudaGetSymbolAddress((void**)&woh, g_woh);  cudaGetSymbolAddress((void**)&wol, g_wol);
    cudaGetSymbolAddress((void**)&w1h, g_w1h);  cudaGetSymbolAddress((void**)&w1l, g_w1l);
    cudaGetSymbolAddress((void**)&w2h, g_w2h);  cudaGetSymbolAddress((void**)&w2l, g_w2l);

    cudaFuncSetAttribute(flash_tc_kernel,
                         cudaFuncAttributeMaxDynamicSharedMemorySize, FLASH_SMEM);

    // 0: fused split of x + all weights
    SplitArgs sa;
    sa.src[0] = x;   sa.hi[0] = xh;  sa.lo[0] = xl;
    sa.src[1] = w_q; sa.hi[1] = wqh; sa.lo[1] = wql;
    sa.src[2] = w_k; sa.hi[2] = wkh; sa.lo[2] = wkl;
    sa.src[3] = w_v; sa.hi[3] = wvh; sa.lo[3] = wvl;
    sa.src[4] = w_o; sa.hi[4] = woh; sa.lo[4] = wol;
    sa.src[5] = w1;  sa.hi[5] = w1h; sa.lo[5] = w1l;
    sa.src[6] = w2;  sa.hi[6] = w2h; sa.lo[6] = w2l;
    split_all_kernel<<<20480, 256>>>(sa);

    // 1: merged QKV GEMM (profiled as process launch 5)
    QKVArgs qa;
    qa.Wh[0] = wqh; qa.Wl[0] = wql; qa.bias[0] = b_q; qa.Ch[0] = qh; qa.Cl[0] = ql;
    qa.Wh[1] = wkh; qa.Wl[1] = wkl; qa.bias[1] = b_k; qa.Ch[1] = kh; qa.Cl[1] = kl;
    qa.Wh[2] = wvh; qa.Wl[2] = wvl; qa.bias[2] = b_v; qa.Ch[2] = vh; qa.Cl[2] = vl;
    qkv_gemm_kernel<<<dim3(Dsz/128, Msz/128, 3), 256>>>(xh, xl, qa);

    // 2: gate
    gate_kernel<<<dim3(Msz/32, 2), 256>>>(x, w_g, b_g, gate);

    // 3: flash attention
    flash_tc_kernel<<<dim3(Ssz/64, Hsz, Bsz), 128, FLASH_SMEM>>>(
        qh, ql, kh, kl, vh, vl, gate, mask, ctxh, ctxl);

    dim3 gSq(Dsz/128, Msz/128);      // (8, 64)
    dim3 gF1(DFFsz/128, Msz/128);    // (32, 64)

    // 4-8: O-proj, LN1, FF1, FF2, LN2
    gemm_bf16x3_kernel<<<gSq, 256>>>(ctxh, ctxl, woh, wol, b_o, tmp, nullptr, nullptr, Dsz, Dsz, 2);
    add_ln_kernel<<<Msz, 256>>>(x, tmp, g1, beta1, x1, x1h, x1l);
    gemm_bf16x3_kernel<<<gF1, 256>>>(x1h, x1l, w1h, w1l, b1, nullptr, ffh, ffl, DFFsz, Dsz, 5);
    gemm_bf16x3_kernel<<<gSq, 256>>>(ffh, ffl, w2h, w2l, b2, tmp, nullptr, nullptr, Dsz, DFFsz, 2);
    add_ln_kernel<<<Msz, 256>>>(x1, tmp, g2, beta2, out, nullptr, nullptr);
}